// round 1
// baseline (speedup 1.0000x reference)
#include <cuda_runtime.h>
#include <math.h>

// Problem constants
#define BB 32
#define SS 196
#define DD 768
#define HH 12
#define DHH 64
#define EE 8
#define FF 3072
#define NT (BB*SS)          // 6272 tokens

// ---------------- device scratch (no allocations allowed) ----------------
__device__ float g_qh[(size_t)NT*DD];
__device__ float g_kh[(size_t)NT*DD];
__device__ float g_vh[(size_t)NT*DD];
__device__ float g_ctx[(size_t)NT*DD];
__device__ float g_attn[(size_t)NT*DD];
__device__ float g_x[(size_t)NT*DD];
__device__ float g_gates[(size_t)NT*EE];
__device__ float g_h[(size_t)EE*NT*FF];     // 616 MB
__device__ float g_y[(size_t)EE*NT*DD];     // 154 MB

// ---------------- SGEMM: C[M,N] = A[M,K] @ B[K,N] + bias[N] (opt gelu) ----
// 128x128 block tile, BK=8, 256 threads, 8x8 per-thread register tile.
// Requires M%128==0, N%128==0, K%8==0 (true for all uses here).
__global__ __launch_bounds__(256)
void sgemm_kernel(const float* __restrict__ A, const float* __restrict__ B,
                  const float* __restrict__ bias, float* __restrict__ C,
                  int M, int N, int K,
                  long long sA, long long sB, long long sBias, long long sC,
                  int gelu)
{
    long long bz = blockIdx.z;
    A    += bz * sA;
    B    += bz * sB;
    bias += bz * sBias;
    C    += bz * sC;

    __shared__ float As[8][128];
    __shared__ float Bs[8][128];

    const int tid = threadIdx.x;
    const int m0 = blockIdx.y * 128;
    const int n0 = blockIdx.x * 128;

    const int arow = tid >> 1;          // 0..127
    const int acol = (tid & 1) * 4;     // 0 or 4
    const int brow = tid >> 5;          // 0..7
    const int bcol = (tid & 31) * 4;    // 0..124
    const int tx = tid & 15;
    const int ty = tid >> 4;

    const float* Aptr = A + (long long)(m0 + arow) * K + acol;
    const float* Bptr = B + (long long)brow * N + n0 + bcol;

    float acc[8][8];
    #pragma unroll
    for (int i = 0; i < 8; i++)
        #pragma unroll
        for (int j = 0; j < 8; j++) acc[i][j] = 0.f;

    for (int k0 = 0; k0 < K; k0 += 8) {
        float4 av = *(const float4*)Aptr;
        float4 bv = *(const float4*)Bptr;
        As[acol + 0][arow] = av.x;
        As[acol + 1][arow] = av.y;
        As[acol + 2][arow] = av.z;
        As[acol + 3][arow] = av.w;
        *(float4*)&Bs[brow][bcol] = bv;
        __syncthreads();

        #pragma unroll
        for (int kk = 0; kk < 8; kk++) {
            float a[8], b[8];
            #pragma unroll
            for (int i = 0; i < 8; i++) a[i] = As[kk][ty * 8 + i];
            #pragma unroll
            for (int j = 0; j < 8; j++) b[j] = Bs[kk][tx * 8 + j];
            #pragma unroll
            for (int i = 0; i < 8; i++)
                #pragma unroll
                for (int j = 0; j < 8; j++)
                    acc[i][j] = fmaf(a[i], b[j], acc[i][j]);
        }
        __syncthreads();
        Aptr += 8;
        Bptr += (long long)8 * N;
    }

    #pragma unroll
    for (int i = 0; i < 8; i++) {
        const long long m = m0 + ty * 8 + i;
        #pragma unroll
        for (int j = 0; j < 8; j += 4) {
            const int n = n0 + tx * 8 + j;
            float4 r;
            r.x = acc[i][j + 0] + bias[n + 0];
            r.y = acc[i][j + 1] + bias[n + 1];
            r.z = acc[i][j + 2] + bias[n + 2];
            r.w = acc[i][j + 3] + bias[n + 3];
            if (gelu) {
                r.x = 0.5f * r.x * (1.f + erff(r.x * 0.70710678118654752f));
                r.y = 0.5f * r.y * (1.f + erff(r.y * 0.70710678118654752f));
                r.z = 0.5f * r.z * (1.f + erff(r.z * 0.70710678118654752f));
                r.w = 0.5f * r.w * (1.f + erff(r.w * 0.70710678118654752f));
            }
            *(float4*)&C[m * N + n] = r;
        }
    }
}

// ---------------- attention: per (b,h) block, full K/V/Q tiles in smem ----
// scores = Qh Kh^T / 8 ; softmax ; ctx = P Vh
__global__ void attn_kernel(const float* __restrict__ qh, const float* __restrict__ kh,
                            const float* __restrict__ vh, float* __restrict__ ctx)
{
    extern __shared__ float sm[];
    float* Qs = sm;                    // 196*65
    float* Ks = Qs + 196 * 65;
    float* Vs = Ks + 196 * 65;
    float* Ps = Vs + 196 * 65;         // 8*196

    const int b = blockIdx.x / HH;
    const int h = blockIdx.x % HH;
    const int tid = threadIdx.x;
    const int lane = tid & 31;
    const int w = tid >> 5;

    const size_t base = ((size_t)b * SS) * DD + (size_t)h * DHH;
    for (int idx = tid; idx < SS * DHH; idx += 256) {
        const int r = idx >> 6, d = idx & 63;
        const size_t g = base + (size_t)r * DD + d;
        Qs[r * 65 + d] = qh[g];
        Ks[r * 65 + d] = kh[g];
        Vs[r * 65 + d] = vh[g];
    }
    __syncthreads();

    for (int q = w; q < SS; q += 8) {
        float sloc[7];
        float mx = -1e30f;
        int cnt = 0;
        for (int k = lane; k < SS; k += 32) {
            const float* qp = &Qs[q * 65];
            const float* kp = &Ks[k * 65];
            float s = 0.f;
            #pragma unroll 16
            for (int d = 0; d < 64; d++) s = fmaf(qp[d], kp[d], s);
            s *= 0.125f;
            sloc[cnt++] = s;
            mx = fmaxf(mx, s);
        }
        #pragma unroll
        for (int off = 16; off; off >>= 1) mx = fmaxf(mx, __shfl_xor_sync(0xffffffffu, mx, off));
        float sum = 0.f;
        cnt = 0;
        for (int k = lane; k < SS; k += 32) {
            float p = __expf(sloc[cnt] - mx);
            sloc[cnt++] = p;
            sum += p;
        }
        #pragma unroll
        for (int off = 16; off; off >>= 1) sum += __shfl_xor_sync(0xffffffffu, sum, off);
        const float inv = 1.f / sum;
        cnt = 0;
        for (int k = lane; k < SS; k += 32) Ps[w * SS + k] = sloc[cnt++] * inv;
        __syncwarp();

        float a0 = 0.f, a1 = 0.f;
        for (int k = 0; k < SS; k++) {
            const float p = Ps[w * SS + k];
            a0 = fmaf(p, Vs[k * 65 + lane], a0);
            a1 = fmaf(p, Vs[k * 65 + lane + 32], a1);
        }
        const size_t o = base + (size_t)q * DD;
        ctx[o + lane]      = a0;
        ctx[o + lane + 32] = a1;
        __syncwarp();
    }
}

// ---------------- block reduce (blockDim == 256) ----------------
__device__ __forceinline__ float block_reduce_sum(float v, float* red)
{
    const int lane = threadIdx.x & 31, w = threadIdx.x >> 5;
    #pragma unroll
    for (int off = 16; off; off >>= 1) v += __shfl_xor_sync(0xffffffffu, v, off);
    if (lane == 0) red[w] = v;
    __syncthreads();
    if (w == 0) {
        float t = (lane < 8) ? red[lane] : 0.f;
        #pragma unroll
        for (int off = 4; off; off >>= 1) t += __shfl_xor_sync(0xffffffffu, t, off);
        if (lane == 0) red[0] = t;
    }
    __syncthreads();
    return red[0];
}

// ---------------- LN1: out = LN(a + b) ----------------
__global__ __launch_bounds__(256)
void ln_add_kernel(const float* __restrict__ a, const float* __restrict__ b,
                   const float* __restrict__ g, const float* __restrict__ beta,
                   float* __restrict__ out)
{
    const int m = blockIdx.x;
    __shared__ float buf[DD];
    __shared__ float red1[32];
    __shared__ float red2[32];
    float s = 0.f;
    for (int d = threadIdx.x; d < DD; d += 256) {
        const float v = a[(size_t)m * DD + d] + b[(size_t)m * DD + d];
        buf[d] = v;
        s += v;
    }
    const float mean = block_reduce_sum(s, red1) * (1.f / DD);
    float s2 = 0.f;
    for (int d = threadIdx.x; d < DD; d += 256) {
        const float t = buf[d] - mean;
        s2 += t * t;
    }
    const float var = block_reduce_sum(s2, red2) * (1.f / DD);
    const float rstd = rsqrtf(var + 1e-5f);
    for (int d = threadIdx.x; d < DD; d += 256)
        out[(size_t)m * DD + d] = (buf[d] - mean) * rstd * g[d] + beta[d];
}

// ---------------- gates = softmax(x @ Wg + bg) over E ----------------
__global__ __launch_bounds__(256)
void gate_kernel(const float* __restrict__ x, const float* __restrict__ Wg,
                 const float* __restrict__ bg, float* __restrict__ gates)
{
    const int m = blockIdx.x;
    const int tid = threadIdx.x, lane = tid & 31, w = tid >> 5;
    float acc[EE] = {0, 0, 0, 0, 0, 0, 0, 0};
    const float* xr = x + (size_t)m * DD;
    for (int d = tid; d < DD; d += 256) {
        const float xv = xr[d];
        #pragma unroll
        for (int e = 0; e < EE; e++) acc[e] = fmaf(xv, Wg[d * EE + e], acc[e]);
    }
    #pragma unroll
    for (int e = 0; e < EE; e++)
        #pragma unroll
        for (int off = 16; off; off >>= 1) acc[e] += __shfl_xor_sync(0xffffffffu, acc[e], off);
    __shared__ float red[8][EE];
    if (lane == 0)
        #pragma unroll
        for (int e = 0; e < EE; e++) red[w][e] = acc[e];
    __syncthreads();
    if (tid == 0) {
        float v[EE];
        float mx = -1e30f;
        for (int e = 0; e < EE; e++) {
            float t = bg[e];
            for (int ww = 0; ww < 8; ww++) t += red[ww][e];
            v[e] = t;
            mx = fmaxf(mx, t);
        }
        float s = 0.f;
        for (int e = 0; e < EE; e++) { v[e] = __expf(v[e] - mx); s += v[e]; }
        const float inv = 1.f / s;
        for (int e = 0; e < EE; e++) gates[(size_t)m * EE + e] = v[e] * inv;
    }
}

// ---------------- LN2: out = LN(x + sum_e gates[e] * y[e]) ----------------
__global__ __launch_bounds__(256)
void ln2_kernel(const float* __restrict__ x, const float* __restrict__ gates,
                const float* __restrict__ y, const float* __restrict__ g,
                const float* __restrict__ beta, float* __restrict__ out)
{
    const int m = blockIdx.x;
    __shared__ float buf[DD];
    __shared__ float gl[EE];
    __shared__ float red1[32];
    __shared__ float red2[32];
    if (threadIdx.x < EE) gl[threadIdx.x] = gates[(size_t)m * EE + threadIdx.x];
    __syncthreads();
    float s = 0.f;
    for (int d = threadIdx.x; d < DD; d += 256) {
        float v = x[(size_t)m * DD + d];
        #pragma unroll
        for (int e = 0; e < EE; e++)
            v = fmaf(gl[e], y[((size_t)e * NT + m) * DD + d], v);
        buf[d] = v;
        s += v;
    }
    const float mean = block_reduce_sum(s, red1) * (1.f / DD);
    float s2 = 0.f;
    for (int d = threadIdx.x; d < DD; d += 256) {
        const float t = buf[d] - mean;
        s2 += t * t;
    }
    const float var = block_reduce_sum(s2, red2) * (1.f / DD);
    const float rstd = rsqrtf(var + 1e-5f);
    for (int d = threadIdx.x; d < DD; d += 256)
        out[(size_t)m * DD + d] = (buf[d] - mean) * rstd * g[d] + beta[d];
}

// ---------------- launch ----------------
extern "C" void kernel_launch(void* const* d_in, const int* in_sizes, int n_in,
                              void* d_out, int out_size)
{
    const float* q    = (const float*)d_in[0];
    const float* k    = (const float*)d_in[1];
    const float* v    = (const float*)d_in[2];
    const float* Wq   = (const float*)d_in[3];
    const float* bq   = (const float*)d_in[4];
    const float* Wk   = (const float*)d_in[5];
    const float* bk   = (const float*)d_in[6];
    const float* Wv   = (const float*)d_in[7];
    const float* bv   = (const float*)d_in[8];
    const float* Wo   = (const float*)d_in[9];
    const float* bo   = (const float*)d_in[10];
    const float* ln1g = (const float*)d_in[11];
    const float* ln1b = (const float*)d_in[12];
    const float* ln2g = (const float*)d_in[13];
    const float* ln2b = (const float*)d_in[14];
    const float* Wg   = (const float*)d_in[15];
    const float* bg   = (const float*)d_in[16];
    const float* W1   = (const float*)d_in[17];
    const float* b1   = (const float*)d_in[18];
    const float* W2   = (const float*)d_in[19];
    const float* b2   = (const float*)d_in[20];
    float* out = (float*)d_out;

    float *qh, *kh, *vh, *ctx, *attn, *x, *gates, *h, *y;
    cudaGetSymbolAddress((void**)&qh,   g_qh);
    cudaGetSymbolAddress((void**)&kh,   g_kh);
    cudaGetSymbolAddress((void**)&vh,   g_vh);
    cudaGetSymbolAddress((void**)&ctx,  g_ctx);
    cudaGetSymbolAddress((void**)&attn, g_attn);
    cudaGetSymbolAddress((void**)&x,    g_x);
    cudaGetSymbolAddress((void**)&gates,g_gates);
    cudaGetSymbolAddress((void**)&h,    g_h);
    cudaGetSymbolAddress((void**)&y,    g_y);

    static int smem_set = 0;
    const int attn_smem = (3 * 196 * 65 + 8 * 196) * (int)sizeof(float); // 159152 B
    if (!smem_set) {
        cudaFuncSetAttribute(attn_kernel, cudaFuncAttributeMaxDynamicSharedMemorySize, attn_smem);
        smem_set = 1;
    }

    const dim3 blk(256);

    // QKV projections: [6272,768] @ [768,768]
    sgemm_kernel<<<dim3(DD/128, NT/128, 1), blk>>>(q, Wq, bq, qh, NT, DD, DD, 0, 0, 0, 0, 0);
    sgemm_kernel<<<dim3(DD/128, NT/128, 1), blk>>>(k, Wk, bk, kh, NT, DD, DD, 0, 0, 0, 0, 0);
    sgemm_kernel<<<dim3(DD/128, NT/128, 1), blk>>>(v, Wv, bv, vh, NT, DD, DD, 0, 0, 0, 0, 0);

    // attention per (b,h)
    attn_kernel<<<BB * HH, blk, attn_smem>>>(qh, kh, vh, ctx);

    // output projection
    sgemm_kernel<<<dim3(DD/128, NT/128, 1), blk>>>(ctx, Wo, bo, attn, NT, DD, DD, 0, 0, 0, 0, 0);

    // LN1(q + attn)
    ln_add_kernel<<<NT, blk>>>(q, attn, ln1g, ln1b, x);

    // gates
    gate_kernel<<<NT, blk>>>(x, Wg, bg, gates);

    // MoE FFN1: h[e] = gelu(x @ W1[e] + b1[e])   [6272,3072] per expert
    sgemm_kernel<<<dim3(FF/128, NT/128, EE), blk>>>(
        x, W1, b1, h, NT, FF, DD,
        0, (long long)DD * FF, (long long)FF, (long long)NT * FF, 1);

    // MoE FFN2: y[e] = h[e] @ W2[e] + b2[e]      [6272,768] per expert
    sgemm_kernel<<<dim3(DD/128, NT/128, EE), blk>>>(
        h, W2, b2, y, NT, DD, FF,
        (long long)NT * FF, (long long)FF * DD, (long long)DD, (long long)NT * DD, 0);

    // LN2(x + sum_e gate_e * y_e)
    ln2_kernel<<<NT, blk>>>(x, gates, y, ln2g, ln2b, out);

    (void)in_sizes; (void)n_in; (void)out_size;
}

// round 3
// speedup vs baseline: 4.1652x; 4.1652x over previous
#include <cuda_runtime.h>
#include <cuda_fp16.h>
#include <math.h>
#include <stdint.h>

// Problem constants
#define BB 32
#define SS 196
#define DD 768
#define HH 12
#define DHH 64
#define EE 8
#define FF 3072
#define NT (BB*SS)          // 6272 tokens

// ---------------------------------------------------------------------------
// helpers
// ---------------------------------------------------------------------------
__device__ __forceinline__ uint32_t smem_u32(const void* p) {
    uint32_t a;
    asm("{ .reg .u64 t; cvta.to.shared.u64 t, %1; cvt.u32.u64 %0, t; }"
        : "=r"(a) : "l"(p));
    return a;
}

__device__ __forceinline__ void cpa16(uint32_t s, const void* g) {
    asm volatile("cp.async.cg.shared.global [%0], [%1], 16;" :: "r"(s), "l"(g));
}
__device__ __forceinline__ void cpa_commit() { asm volatile("cp.async.commit_group;"); }
template<int N> __device__ __forceinline__ void cpa_wait() {
    asm volatile("cp.async.wait_group %0;" :: "n"(N));
}

#define LDMX4(r, addr) \
    asm volatile("ldmatrix.sync.aligned.m8n8.x4.shared.b16 {%0,%1,%2,%3}, [%4];" \
        : "=r"((r)[0]), "=r"((r)[1]), "=r"((r)[2]), "=r"((r)[3]) : "r"(addr))

__device__ __forceinline__ void mma16816(float* d, const uint32_t* a, const uint32_t* b) {
    asm volatile("mma.sync.aligned.m16n8k16.row.col.f32.f16.f16.f32 "
        "{%0,%1,%2,%3}, {%4,%5,%6,%7}, {%8,%9}, {%0,%1,%2,%3};"
        : "+f"(d[0]), "+f"(d[1]), "+f"(d[2]), "+f"(d[3])
        : "r"(a[0]), "r"(a[1]), "r"(a[2]), "r"(a[3]), "r"(b[0]), "r"(b[1]));
}

__device__ __forceinline__ float gelu_exact(float v) {
    return 0.5f * v * (1.f + erff(v * 0.70710678118654752f));
}

// ---------------------------------------------------------------------------
// device scratch (static: no runtime allocations allowed)
// ---------------------------------------------------------------------------
__device__ __half g_qa[(size_t)NT*DD];
__device__ __half g_ka[(size_t)NT*DD];
__device__ __half g_va[(size_t)NT*DD];
__device__ float  g_qh[(size_t)NT*DD];
__device__ float  g_kh[(size_t)NT*DD];
__device__ float  g_vh[(size_t)NT*DD];
__device__ __half g_ctx[(size_t)NT*DD];
__device__ float  g_attn[(size_t)NT*DD];
__device__ float  g_x[(size_t)NT*DD];
__device__ __half g_xh[(size_t)NT*DD];
__device__ float  g_gates[(size_t)NT*EE];
__device__ __half g_hact[(size_t)EE*NT*FF];   // 308 MB
__device__ float  g_y[(size_t)EE*NT*DD];
// transposed fp16 weights [N,K]
__device__ __half g_WqT[(size_t)DD*DD];
__device__ __half g_WkT[(size_t)DD*DD];
__device__ __half g_WvT[(size_t)DD*DD];
__device__ __half g_WoT[(size_t)DD*DD];
__device__ __half g_W1T[(size_t)EE*FF*DD];
__device__ __half g_W2T[(size_t)EE*DD*FF];

// ---------------------------------------------------------------------------
// conversion kernels
// ---------------------------------------------------------------------------
__global__ __launch_bounds__(256)
void convert_h_kernel(const float* __restrict__ in, __half* __restrict__ o, long long n)
{
    long long i = (long long)blockIdx.x * blockDim.x + threadIdx.x;
    const long long stride = (long long)gridDim.x * blockDim.x;
    for (; i < n; i += stride) o[i] = __float2half_rn(in[i]);
}

// in: [batch, K, N] fp32  ->  out: [batch, N, K] fp16
__global__ __launch_bounds__(256)
void transpose_h_kernel(const float* __restrict__ in, __half* __restrict__ o, int K, int N)
{
    __shared__ float t[32][33];
    const size_t bz = blockIdx.z;
    const float* ip = in + bz * (size_t)K * N;
    __half* op = o + bz * (size_t)K * N;
    const int k0 = blockIdx.y * 32, n0 = blockIdx.x * 32;
    const int tx = threadIdx.x, ty = threadIdx.y;
    #pragma unroll
    for (int j = 0; j < 4; j++)
        t[ty + j * 8][tx] = ip[(size_t)(k0 + ty + j * 8) * N + n0 + tx];
    __syncthreads();
    #pragma unroll
    for (int j = 0; j < 4; j++)
        op[(size_t)(n0 + ty + j * 8) * K + k0 + tx] = __float2half_rn(t[tx][ty + j * 8]);
}

// ---------------------------------------------------------------------------
// HMMA fp16 GEMM:  C[M,N] = A[M,K] @ B[N,K]^T + bias[N]
//   EPI 0: fp32 out.   EPI 1: gelu -> fp16 out.
// BM=128 BN=128 BK=32, 256 threads, warp grid 2(m) x 4(n), warp tile 64x32.
// 3-stage cp.async pipeline. smem rows padded to 40 halfs (80B) -> ldmatrix
// row addresses land on 8 disjoint 4-bank groups (conflict-free).
// ---------------------------------------------------------------------------
#define GBM 128
#define GBN 128
#define GBK 32
#define ROWH 40
#define TILE_BYTES (128 * ROWH * 2)       // 10240
#define STAGE_BYTES (2 * TILE_BYTES)      // 20480
#define NSTAGE 3
#define GEMM_SMEM (NSTAGE * STAGE_BYTES)  // 61440

template<int EPI>
__global__ __launch_bounds__(256, 1)
void gemm_f16(const __half* __restrict__ A, const __half* __restrict__ B,
              const float* __restrict__ bias,
              float* __restrict__ C, __half* __restrict__ Ch,
              int K, int ldC,
              long long strA, long long strB, long long strBias, long long strC)
{
    extern __shared__ char smem[];
    const uint32_t smem_base = smem_u32(smem);

    const int tid = threadIdx.x;
    const int lane = tid & 31;
    const int wid = tid >> 5;
    const int wm = wid & 1;           // 0..1
    const int wn = wid >> 1;          // 0..3

    const long long bz = blockIdx.z;
    A += bz * strA;
    B += bz * strB;
    bias += bz * strBias;

    const int m0 = blockIdx.y * GBM;
    const int n0 = blockIdx.x * GBN;
    const int NC = K / GBK;

    // ---- stage loader: A tile [128][32], B tile [128][32], both K-major ----
    auto load_stage = [&](int kc, int st) {
        const uint32_t sb = smem_base + st * STAGE_BYTES;
        const long long k0 = (long long)kc * GBK;
        #pragma unroll
        for (int i = tid; i < 512; i += 256) {
            const int r = i >> 2;
            const int c = (i & 3) * 8;
            cpa16(sb + r * 80 + c * 2, A + (size_t)(m0 + r) * K + k0 + c);
        }
        #pragma unroll
        for (int i = tid; i < 512; i += 256) {
            const int r = i >> 2;
            const int c = (i & 3) * 8;
            cpa16(sb + TILE_BYTES + r * 80 + c * 2, B + (size_t)(n0 + r) * K + k0 + c);
        }
        cpa_commit();
    };

    load_stage(0, 0);
    if (NC > 1) load_stage(1, 1);

    float acc[4][4][4];
    #pragma unroll
    for (int i = 0; i < 4; i++)
        #pragma unroll
        for (int j = 0; j < 4; j++)
            #pragma unroll
            for (int r = 0; r < 4; r++) acc[i][j][r] = 0.f;

    // ldmatrix lane address components (constant per thread)
    const int a_row_in16 = lane & 15;           // row within 16-row subtile
    const int a_col8 = (lane >> 4) * 8;         // 0 or 8 (k offset)
    const int b_row_in16 = ((lane >> 4) << 3) + (lane & 7);
    const int b_col8 = ((lane >> 3) & 1) * 8;

    for (int kc = 0; kc < NC; kc++) {
        cpa_wait<NSTAGE - 2>();
        __syncthreads();

        const uint32_t sa = smem_base + (kc % NSTAGE) * STAGE_BYTES;
        const uint32_t sb = sa + TILE_BYTES;

        #pragma unroll
        for (int ks = 0; ks < 2; ks++) {
            uint32_t af[4][4];
            uint32_t bf[4][2];
            #pragma unroll
            for (int ms = 0; ms < 4; ms++) {
                const uint32_t addr = sa
                    + (uint32_t)(wm * 64 + ms * 16 + a_row_in16) * 80
                    + (uint32_t)(a_col8 + ks * 16) * 2;
                LDMX4(af[ms], addr);
            }
            #pragma unroll
            for (int bs = 0; bs < 2; bs++) {
                uint32_t r[4];
                const uint32_t addr = sb
                    + (uint32_t)(wn * 32 + bs * 16 + b_row_in16) * 80
                    + (uint32_t)(b_col8 + ks * 16) * 2;
                LDMX4(r, addr);
                bf[2 * bs][0] = r[0]; bf[2 * bs][1] = r[1];
                bf[2 * bs + 1][0] = r[2]; bf[2 * bs + 1][1] = r[3];
            }
            #pragma unroll
            for (int ms = 0; ms < 4; ms++)
                #pragma unroll
                for (int ns = 0; ns < 4; ns++)
                    mma16816(acc[ms][ns], af[ms], bf[ns]);
        }

        if (kc + NSTAGE - 1 < NC)
            load_stage(kc + NSTAGE - 1, (kc + NSTAGE - 1) % NSTAGE);
    }

    // ---- epilogue ----
    const int row_g = lane >> 2;          // 0..7
    const int col_g = (lane & 3) * 2;     // 0,2,4,6
    #pragma unroll
    for (int ms = 0; ms < 4; ms++) {
        #pragma unroll
        for (int ns = 0; ns < 4; ns++) {
            const int n = n0 + wn * 32 + ns * 8 + col_g;
            const float b0 = bias[n], b1 = bias[n + 1];
            const int mA = m0 + wm * 64 + ms * 16 + row_g;
            const int mB = mA + 8;
            if (EPI == 0) {
                float* Cb = C + bz * strC;
                float2 o0, o1;
                o0.x = acc[ms][ns][0] + b0;  o0.y = acc[ms][ns][1] + b1;
                o1.x = acc[ms][ns][2] + b0;  o1.y = acc[ms][ns][3] + b1;
                *(float2*)&Cb[(size_t)mA * ldC + n] = o0;
                *(float2*)&Cb[(size_t)mB * ldC + n] = o1;
            } else {
                __half* Cb = Ch + bz * strC;
                __half2 o0, o1;
                o0.x = __float2half_rn(gelu_exact(acc[ms][ns][0] + b0));
                o0.y = __float2half_rn(gelu_exact(acc[ms][ns][1] + b1));
                o1.x = __float2half_rn(gelu_exact(acc[ms][ns][2] + b0));
                o1.y = __float2half_rn(gelu_exact(acc[ms][ns][3] + b1));
                *(__half2*)&Cb[(size_t)mA * ldC + n] = o0;
                *(__half2*)&Cb[(size_t)mB * ldC + n] = o1;
            }
        }
    }
}

// ---------------------------------------------------------------------------
// attention: per (b,h) block, fp32 math, fp16 ctx out
// ---------------------------------------------------------------------------
__global__ void attn_kernel(const float* __restrict__ qh, const float* __restrict__ kh,
                            const float* __restrict__ vh, __half* __restrict__ ctx)
{
    extern __shared__ float sm[];
    float* Qs = sm;
    float* Ks = Qs + 196 * 65;
    float* Vs = Ks + 196 * 65;
    float* Ps = Vs + 196 * 65;

    const int b = blockIdx.x / HH;
    const int h = blockIdx.x % HH;
    const int tid = threadIdx.x;
    const int lane = tid & 31;
    const int w = tid >> 5;

    const size_t base = ((size_t)b * SS) * DD + (size_t)h * DHH;
    for (int idx = tid; idx < SS * DHH; idx += 256) {
        const int r = idx >> 6, d = idx & 63;
        const size_t g = base + (size_t)r * DD + d;
        Qs[r * 65 + d] = qh[g];
        Ks[r * 65 + d] = kh[g];
        Vs[r * 65 + d] = vh[g];
    }
    __syncthreads();

    for (int q = w; q < SS; q += 8) {
        float sloc[7];
        float mx = -1e30f;
        int cnt = 0;
        for (int k = lane; k < SS; k += 32) {
            const float* qp = &Qs[q * 65];
            const float* kp = &Ks[k * 65];
            float s = 0.f;
            #pragma unroll 16
            for (int d = 0; d < 64; d++) s = fmaf(qp[d], kp[d], s);
            s *= 0.125f;
            sloc[cnt++] = s;
            mx = fmaxf(mx, s);
        }
        #pragma unroll
        for (int off = 16; off; off >>= 1) mx = fmaxf(mx, __shfl_xor_sync(0xffffffffu, mx, off));
        float sum = 0.f;
        cnt = 0;
        for (int k = lane; k < SS; k += 32) {
            float p = __expf(sloc[cnt] - mx);
            sloc[cnt++] = p;
            sum += p;
        }
        #pragma unroll
        for (int off = 16; off; off >>= 1) sum += __shfl_xor_sync(0xffffffffu, sum, off);
        const float inv = 1.f / sum;
        cnt = 0;
        for (int k = lane; k < SS; k += 32) Ps[w * SS + k] = sloc[cnt++] * inv;
        __syncwarp();

        float a0 = 0.f, a1 = 0.f;
        for (int k = 0; k < SS; k++) {
            const float p = Ps[w * SS + k];
            a0 = fmaf(p, Vs[k * 65 + lane], a0);
            a1 = fmaf(p, Vs[k * 65 + lane + 32], a1);
        }
        const size_t o = base + (size_t)q * DD;
        ctx[o + lane]      = __float2half_rn(a0);
        ctx[o + lane + 32] = __float2half_rn(a1);
        __syncwarp();
    }
}

// ---------------------------------------------------------------------------
// LN / gate kernels
// ---------------------------------------------------------------------------
__device__ __forceinline__ float block_reduce_sum(float v, float* red)
{
    const int lane = threadIdx.x & 31, w = threadIdx.x >> 5;
    #pragma unroll
    for (int off = 16; off; off >>= 1) v += __shfl_xor_sync(0xffffffffu, v, off);
    if (lane == 0) red[w] = v;
    __syncthreads();
    if (w == 0) {
        float t = (lane < 8) ? red[lane] : 0.f;
        #pragma unroll
        for (int off = 4; off; off >>= 1) t += __shfl_xor_sync(0xffffffffu, t, off);
        if (lane == 0) red[0] = t;
    }
    __syncthreads();
    return red[0];
}

// LN1: x = LN(a + b); also emits fp16 copy of x
__global__ __launch_bounds__(256)
void ln1_kernel(const float* __restrict__ a, const float* __restrict__ b,
                const float* __restrict__ g, const float* __restrict__ beta,
                float* __restrict__ out, __half* __restrict__ oh)
{
    const int m = blockIdx.x;
    __shared__ float buf[DD];
    __shared__ float red1[32];
    __shared__ float red2[32];
    float s = 0.f;
    for (int d = threadIdx.x; d < DD; d += 256) {
        const float v = a[(size_t)m * DD + d] + b[(size_t)m * DD + d];
        buf[d] = v;
        s += v;
    }
    const float mean = block_reduce_sum(s, red1) * (1.f / DD);
    float s2 = 0.f;
    for (int d = threadIdx.x; d < DD; d += 256) {
        const float t = buf[d] - mean;
        s2 += t * t;
    }
    const float var = block_reduce_sum(s2, red2) * (1.f / DD);
    const float rstd = rsqrtf(var + 1e-5f);
    for (int d = threadIdx.x; d < DD; d += 256) {
        const float v = (buf[d] - mean) * rstd * g[d] + beta[d];
        out[(size_t)m * DD + d] = v;
        oh[(size_t)m * DD + d] = __float2half_rn(v);
    }
}

__global__ __launch_bounds__(256)
void gate_kernel(const float* __restrict__ x, const float* __restrict__ Wg,
                 const float* __restrict__ bg, float* __restrict__ gates)
{
    const int m = blockIdx.x;
    const int tid = threadIdx.x, lane = tid & 31, w = tid >> 5;
    float acc[EE] = {0, 0, 0, 0, 0, 0, 0, 0};
    const float* xr = x + (size_t)m * DD;
    for (int d = tid; d < DD; d += 256) {
        const float xv = xr[d];
        #pragma unroll
        for (int e = 0; e < EE; e++) acc[e] = fmaf(xv, Wg[d * EE + e], acc[e]);
    }
    #pragma unroll
    for (int e = 0; e < EE; e++)
        #pragma unroll
        for (int off = 16; off; off >>= 1) acc[e] += __shfl_xor_sync(0xffffffffu, acc[e], off);
    __shared__ float red[8][EE];
    if (lane == 0)
        #pragma unroll
        for (int e = 0; e < EE; e++) red[w][e] = acc[e];
    __syncthreads();
    if (tid == 0) {
        float v[EE];
        float mx = -1e30f;
        for (int e = 0; e < EE; e++) {
            float t = bg[e];
            for (int ww = 0; ww < 8; ww++) t += red[ww][e];
            v[e] = t;
            mx = fmaxf(mx, t);
        }
        float s = 0.f;
        for (int e = 0; e < EE; e++) { v[e] = __expf(v[e] - mx); s += v[e]; }
        const float inv = 1.f / s;
        for (int e = 0; e < EE; e++) gates[(size_t)m * EE + e] = v[e] * inv;
    }
}

__global__ __launch_bounds__(256)
void ln2_kernel(const float* __restrict__ x, const float* __restrict__ gates,
                const float* __restrict__ y, const float* __restrict__ g,
                const float* __restrict__ beta, float* __restrict__ out)
{
    const int m = blockIdx.x;
    __shared__ float buf[DD];
    __shared__ float gl[EE];
    __shared__ float red1[32];
    __shared__ float red2[32];
    if (threadIdx.x < EE) gl[threadIdx.x] = gates[(size_t)m * EE + threadIdx.x];
    __syncthreads();
    float s = 0.f;
    for (int d = threadIdx.x; d < DD; d += 256) {
        float v = x[(size_t)m * DD + d];
        #pragma unroll
        for (int e = 0; e < EE; e++)
            v = fmaf(gl[e], y[((size_t)e * NT + m) * DD + d], v);
        buf[d] = v;
        s += v;
    }
    const float mean = block_reduce_sum(s, red1) * (1.f / DD);
    float s2 = 0.f;
    for (int d = threadIdx.x; d < DD; d += 256) {
        const float t = buf[d] - mean;
        s2 += t * t;
    }
    const float var = block_reduce_sum(s2, red2) * (1.f / DD);
    const float rstd = rsqrtf(var + 1e-5f);
    for (int d = threadIdx.x; d < DD; d += 256)
        out[(size_t)m * DD + d] = (buf[d] - mean) * rstd * g[d] + beta[d];
}

// ---------------------------------------------------------------------------
// launch
// ---------------------------------------------------------------------------
extern "C" void kernel_launch(void* const* d_in, const int* in_sizes, int n_in,
                              void* d_out, int out_size)
{
    const float* q    = (const float*)d_in[0];
    const float* k    = (const float*)d_in[1];
    const float* v    = (const float*)d_in[2];
    const float* Wq   = (const float*)d_in[3];
    const float* bq   = (const float*)d_in[4];
    const float* Wk   = (const float*)d_in[5];
    const float* bk   = (const float*)d_in[6];
    const float* Wv   = (const float*)d_in[7];
    const float* bv   = (const float*)d_in[8];
    const float* Wo   = (const float*)d_in[9];
    const float* bo   = (const float*)d_in[10];
    const float* ln1g = (const float*)d_in[11];
    const float* ln1b = (const float*)d_in[12];
    const float* ln2g = (const float*)d_in[13];
    const float* ln2b = (const float*)d_in[14];
    const float* Wg   = (const float*)d_in[15];
    const float* bg   = (const float*)d_in[16];
    const float* W1   = (const float*)d_in[17];
    const float* b1   = (const float*)d_in[18];
    const float* W2   = (const float*)d_in[19];
    const float* b2   = (const float*)d_in[20];
    float* out = (float*)d_out;

    __half *qa, *ka, *va, *ctx, *xh, *hact;
    __half *WqT, *WkT, *WvT, *WoT, *W1T, *W2T;
    float *qh, *kh, *vh, *attn, *x, *gates, *y;
    cudaGetSymbolAddress((void**)&qa, g_qa);
    cudaGetSymbolAddress((void**)&ka, g_ka);
    cudaGetSymbolAddress((void**)&va, g_va);
    cudaGetSymbolAddress((void**)&qh, g_qh);
    cudaGetSymbolAddress((void**)&kh, g_kh);
    cudaGetSymbolAddress((void**)&vh, g_vh);
    cudaGetSymbolAddress((void**)&ctx, g_ctx);
    cudaGetSymbolAddress((void**)&attn, g_attn);
    cudaGetSymbolAddress((void**)&x, g_x);
    cudaGetSymbolAddress((void**)&xh, g_xh);
    cudaGetSymbolAddress((void**)&gates, g_gates);
    cudaGetSymbolAddress((void**)&hact, g_hact);
    cudaGetSymbolAddress((void**)&y, g_y);
    cudaGetSymbolAddress((void**)&WqT, g_WqT);
    cudaGetSymbolAddress((void**)&WkT, g_WkT);
    cudaGetSymbolAddress((void**)&WvT, g_WvT);
    cudaGetSymbolAddress((void**)&WoT, g_WoT);
    cudaGetSymbolAddress((void**)&W1T, g_W1T);
    cudaGetSymbolAddress((void**)&W2T, g_W2T);

    const int attn_smem = (3 * 196 * 65 + 8 * 196) * (int)sizeof(float);
    cudaFuncSetAttribute(attn_kernel, cudaFuncAttributeMaxDynamicSharedMemorySize, attn_smem);
    cudaFuncSetAttribute(gemm_f16<0>, cudaFuncAttributeMaxDynamicSharedMemorySize, GEMM_SMEM);
    cudaFuncSetAttribute(gemm_f16<1>, cudaFuncAttributeMaxDynamicSharedMemorySize, GEMM_SMEM);

    const dim3 blk(256);
    const long long nAct = (long long)NT * DD;

    // 1) convert inputs to fp16
    convert_h_kernel<<<1024, blk>>>(q, qa, nAct);
    convert_h_kernel<<<1024, blk>>>(k, ka, nAct);
    convert_h_kernel<<<1024, blk>>>(v, va, nAct);

    // 2) transpose + convert weights ([K,N] -> [N,K] fp16)
    transpose_h_kernel<<<dim3(DD/32, DD/32, 1), dim3(32, 8)>>>(Wq, WqT, DD, DD);
    transpose_h_kernel<<<dim3(DD/32, DD/32, 1), dim3(32, 8)>>>(Wk, WkT, DD, DD);
    transpose_h_kernel<<<dim3(DD/32, DD/32, 1), dim3(32, 8)>>>(Wv, WvT, DD, DD);
    transpose_h_kernel<<<dim3(DD/32, DD/32, 1), dim3(32, 8)>>>(Wo, WoT, DD, DD);
    transpose_h_kernel<<<dim3(FF/32, DD/32, EE), dim3(32, 8)>>>(W1, W1T, DD, FF);
    transpose_h_kernel<<<dim3(DD/32, FF/32, EE), dim3(32, 8)>>>(W2, W2T, FF, DD);

    // 3) QKV projections
    gemm_f16<0><<<dim3(DD/GBN, NT/GBM, 1), blk, GEMM_SMEM>>>(
        qa, WqT, bq, qh, nullptr, DD, DD, 0, 0, 0, 0);
    gemm_f16<0><<<dim3(DD/GBN, NT/GBM, 1), blk, GEMM_SMEM>>>(
        ka, WkT, bk, kh, nullptr, DD, DD, 0, 0, 0, 0);
    gemm_f16<0><<<dim3(DD/GBN, NT/GBM, 1), blk, GEMM_SMEM>>>(
        va, WvT, bv, vh, nullptr, DD, DD, 0, 0, 0, 0);

    // 4) attention
    attn_kernel<<<BB * HH, blk, attn_smem>>>(qh, kh, vh, ctx);

    // 5) output projection
    gemm_f16<0><<<dim3(DD/GBN, NT/GBM, 1), blk, GEMM_SMEM>>>(
        ctx, WoT, bo, attn, nullptr, DD, DD, 0, 0, 0, 0);

    // 6) LN1 + fp16 copy
    ln1_kernel<<<NT, blk>>>(q, attn, ln1g, ln1b, x, xh);

    // 7) gates
    gate_kernel<<<NT, blk>>>(x, Wg, bg, gates);

    // 8) MoE FFN1 (gelu -> fp16)
    gemm_f16<1><<<dim3(FF/GBN, NT/GBM, EE), blk, GEMM_SMEM>>>(
        xh, W1T, b1, nullptr, hact, DD, FF,
        0, (long long)FF * DD, (long long)FF, (long long)NT * FF);

    // 9) MoE FFN2
    gemm_f16<0><<<dim3(DD/GBN, NT/GBM, EE), blk, GEMM_SMEM>>>(
        hact, W2T, b2, y, nullptr, FF, DD,
        (long long)NT * FF, (long long)DD * FF, (long long)DD, (long long)NT * DD);

    // 10) LN2
    ln2_kernel<<<NT, blk>>>(x, gates, y, ln2g, ln2b, out);

    (void)in_sizes; (void)n_in; (void)out_size;
}

// round 4
// speedup vs baseline: 5.7880x; 1.3896x over previous
#include <cuda_runtime.h>
#include <cuda_fp16.h>
#include <math.h>
#include <stdint.h>

// Problem constants
#define BB 32
#define SS 196
#define DD 768
#define HH 12
#define DHH 64
#define EE 8
#define FF 3072
#define NT (BB*SS)          // 6272 tokens

// ---------------------------------------------------------------------------
// helpers
// ---------------------------------------------------------------------------
__device__ __forceinline__ uint32_t smem_u32(const void* p) {
    uint32_t a;
    asm("{ .reg .u64 t; cvta.to.shared.u64 t, %1; cvt.u32.u64 %0, t; }"
        : "=r"(a) : "l"(p));
    return a;
}

__device__ __forceinline__ void cpa16(uint32_t s, const void* g) {
    asm volatile("cp.async.cg.shared.global [%0], [%1], 16;" :: "r"(s), "l"(g));
}
__device__ __forceinline__ void cpa_commit() { asm volatile("cp.async.commit_group;"); }
template<int N> __device__ __forceinline__ void cpa_wait() {
    asm volatile("cp.async.wait_group %0;" :: "n"(N));
}

#define LDMX4(r, addr) \
    asm volatile("ldmatrix.sync.aligned.m8n8.x4.shared.b16 {%0,%1,%2,%3}, [%4];" \
        : "=r"((r)[0]), "=r"((r)[1]), "=r"((r)[2]), "=r"((r)[3]) : "r"(addr))

__device__ __forceinline__ void mma16816(float* d, const uint32_t* a, const uint32_t* b) {
    asm volatile("mma.sync.aligned.m16n8k16.row.col.f32.f16.f16.f32 "
        "{%0,%1,%2,%3}, {%4,%5,%6,%7}, {%8,%9}, {%0,%1,%2,%3};"
        : "+f"(d[0]), "+f"(d[1]), "+f"(d[2]), "+f"(d[3])
        : "r"(a[0]), "r"(a[1]), "r"(a[2]), "r"(a[3]), "r"(b[0]), "r"(b[1]));
}

__device__ __forceinline__ float gelu_exact(float v) {
    return 0.5f * v * (1.f + erff(v * 0.70710678118654752f));
}

// ---------------------------------------------------------------------------
// device scratch
// ---------------------------------------------------------------------------
__device__ __half g_qa[(size_t)NT*DD];
__device__ __half g_ka[(size_t)NT*DD];
__device__ __half g_va[(size_t)NT*DD];
__device__ float  g_qh[(size_t)NT*DD];
__device__ float  g_kh[(size_t)NT*DD];
__device__ float  g_vh[(size_t)NT*DD];
__device__ __half g_ctx[(size_t)NT*DD];
__device__ float  g_attn[(size_t)NT*DD];
__device__ float  g_x[(size_t)NT*DD];
__device__ __half g_xh[(size_t)NT*DD];
__device__ float  g_gates[(size_t)NT*EE];
__device__ __half g_hact[(size_t)EE*NT*FF];   // 308 MB
__device__ float  g_y[(size_t)EE*NT*DD];
__device__ __half g_WqT[(size_t)DD*DD];
__device__ __half g_WkT[(size_t)DD*DD];
__device__ __half g_WvT[(size_t)DD*DD];
__device__ __half g_WoT[(size_t)DD*DD];
__device__ __half g_W1T[(size_t)EE*FF*DD];
__device__ __half g_W2T[(size_t)EE*DD*FF];

// ---------------------------------------------------------------------------
// conversion kernels
// ---------------------------------------------------------------------------
__global__ __launch_bounds__(256)
void convert_h_kernel(const float* __restrict__ in, __half* __restrict__ o, long long n)
{
    long long i = (long long)blockIdx.x * blockDim.x + threadIdx.x;
    const long long stride = (long long)gridDim.x * blockDim.x;
    for (; i < n; i += stride) o[i] = __float2half_rn(in[i]);
}

// in: [batch, K, N] fp32  ->  out: [batch, N, K] fp16
__global__ __launch_bounds__(256)
void transpose_h_kernel(const float* __restrict__ in, __half* __restrict__ o, int K, int N)
{
    __shared__ float t[32][33];
    const size_t bz = blockIdx.z;
    const float* ip = in + bz * (size_t)K * N;
    __half* op = o + bz * (size_t)K * N;
    const int k0 = blockIdx.y * 32, n0 = blockIdx.x * 32;
    const int tx = threadIdx.x, ty = threadIdx.y;
    #pragma unroll
    for (int j = 0; j < 4; j++)
        t[ty + j * 8][tx] = ip[(size_t)(k0 + ty + j * 8) * N + n0 + tx];
    __syncthreads();
    #pragma unroll
    for (int j = 0; j < 4; j++)
        op[(size_t)(n0 + ty + j * 8) * K + k0 + tx] = __float2half_rn(t[tx][ty + j * 8]);
}

// ---------------------------------------------------------------------------
// HMMA fp16 GEMM: C[M,N] = A[M,K] @ B[N,K]^T + bias[N]
// BM=128 BN=256 BK=32, 256 threads, warp grid 2(m) x 4(n), warp tile 64x64.
// 4-stage cp.async pipeline, padded 80B smem rows (ldmatrix conflict-free).
// EPI 0: fp32 out.   EPI 1: gelu -> fp16 out.
// ---------------------------------------------------------------------------
#define GBM 128
#define GBN 256
#define GBK 32
#define TILE_A (128 * 80)                  // 10240
#define TILE_B (256 * 80)                  // 20480
#define STAGE_BYTES (TILE_A + TILE_B)      // 30720
#define NSTAGE 4
#define GEMM_SMEM (NSTAGE * STAGE_BYTES)   // 122880

template<int EPI>
__global__ __launch_bounds__(256, 1)
void gemm_f16(const __half* __restrict__ A, const __half* __restrict__ B,
              const float* __restrict__ bias,
              float* __restrict__ C, __half* __restrict__ Ch,
              int K, int ldC,
              long long strA, long long strB, long long strBias, long long strC)
{
    extern __shared__ char smem[];
    const uint32_t smem_base = smem_u32(smem);

    const int tid = threadIdx.x;
    const int lane = tid & 31;
    const int wid = tid >> 5;
    const int wm = wid & 1;           // 0..1  (64 rows each)
    const int wn = wid >> 1;          // 0..3  (64 cols each)

    const long long bz = blockIdx.z;
    A += bz * strA;
    B += bz * strB;
    bias += bz * strBias;

    const int m0 = blockIdx.y * GBM;
    const int n0 = blockIdx.x * GBN;
    const int NC = K / GBK;           // always >= 3 here

    auto load_stage = [&](int kc, int st) {
        const uint32_t sb = smem_base + st * STAGE_BYTES;
        const long long k0 = (long long)kc * GBK;
        #pragma unroll
        for (int i = tid; i < 512; i += 256) {            // A: 128 rows x 4 vec16
            const int r = i >> 2;
            const int c = (i & 3) * 8;
            cpa16(sb + r * 80 + c * 2, A + (size_t)(m0 + r) * K + k0 + c);
        }
        #pragma unroll
        for (int i = tid; i < 1024; i += 256) {           // B: 256 rows x 4 vec16
            const int r = i >> 2;
            const int c = (i & 3) * 8;
            cpa16(sb + TILE_A + r * 80 + c * 2, B + (size_t)(n0 + r) * K + k0 + c);
        }
        cpa_commit();
    };

    load_stage(0, 0);
    load_stage(1, 1);
    load_stage(2, 2);

    float acc[4][8][4];
    #pragma unroll
    for (int i = 0; i < 4; i++)
        #pragma unroll
        for (int j = 0; j < 8; j++)
            #pragma unroll
            for (int r = 0; r < 4; r++) acc[i][j][r] = 0.f;

    const int a_row_in16 = lane & 15;
    const int a_col8 = (lane >> 4) * 8;
    const int b_row_in16 = ((lane >> 4) << 3) + (lane & 7);
    const int b_col8 = ((lane >> 3) & 1) * 8;

    for (int kc = 0; kc < NC; kc++) {
        cpa_wait<NSTAGE - 2>();
        __syncthreads();

        const uint32_t sa = smem_base + (kc % NSTAGE) * STAGE_BYTES;
        const uint32_t sbB = sa + TILE_A;

        #pragma unroll
        for (int ks = 0; ks < 2; ks++) {
            uint32_t af[4][4];
            uint32_t bf[8][2];
            #pragma unroll
            for (int ms = 0; ms < 4; ms++) {
                const uint32_t addr = sa
                    + (uint32_t)(wm * 64 + ms * 16 + a_row_in16) * 80
                    + (uint32_t)(a_col8 + ks * 16) * 2;
                LDMX4(af[ms], addr);
            }
            #pragma unroll
            for (int bs = 0; bs < 4; bs++) {
                uint32_t r[4];
                const uint32_t addr = sbB
                    + (uint32_t)(wn * 64 + bs * 16 + b_row_in16) * 80
                    + (uint32_t)(b_col8 + ks * 16) * 2;
                LDMX4(r, addr);
                bf[2 * bs][0] = r[0]; bf[2 * bs][1] = r[1];
                bf[2 * bs + 1][0] = r[2]; bf[2 * bs + 1][1] = r[3];
            }
            #pragma unroll
            for (int ms = 0; ms < 4; ms++)
                #pragma unroll
                for (int ns = 0; ns < 8; ns++)
                    mma16816(acc[ms][ns], af[ms], bf[ns]);
        }

        if (kc + NSTAGE - 1 < NC)
            load_stage(kc + NSTAGE - 1, (kc + NSTAGE - 1) % NSTAGE);
    }

    // ---- epilogue ----
    const int row_g = lane >> 2;
    const int col_g = (lane & 3) * 2;
    #pragma unroll
    for (int ms = 0; ms < 4; ms++) {
        #pragma unroll
        for (int ns = 0; ns < 8; ns++) {
            const int n = n0 + wn * 64 + ns * 8 + col_g;
            const float b0 = bias[n], b1 = bias[n + 1];
            const int mA = m0 + wm * 64 + ms * 16 + row_g;
            const int mB = mA + 8;
            if (EPI == 0) {
                float* Cb = C + bz * strC;
                float2 o0, o1;
                o0.x = acc[ms][ns][0] + b0;  o0.y = acc[ms][ns][1] + b1;
                o1.x = acc[ms][ns][2] + b0;  o1.y = acc[ms][ns][3] + b1;
                *(float2*)&Cb[(size_t)mA * ldC + n] = o0;
                *(float2*)&Cb[(size_t)mB * ldC + n] = o1;
            } else {
                __half* Cb = Ch + bz * strC;
                __half2 o0, o1;
                o0.x = __float2half_rn(gelu_exact(acc[ms][ns][0] + b0));
                o0.y = __float2half_rn(gelu_exact(acc[ms][ns][1] + b1));
                o1.x = __float2half_rn(gelu_exact(acc[ms][ns][2] + b0));
                o1.y = __float2half_rn(gelu_exact(acc[ms][ns][3] + b1));
                *(__half2*)&Cb[(size_t)mA * ldC + n] = o0;
                *(__half2*)&Cb[(size_t)mB * ldC + n] = o1;
            }
        }
    }
}

// ---------------------------------------------------------------------------
// attention: per (b,h) block, 4-query blocking + float4 LDS, fp16 ctx out
// smem: Q/K/V [196][68] fp32 + P [32][196]
// ---------------------------------------------------------------------------
#define AROW 68
#define ATTN_SMEM ((3 * SS * AROW + 32 * SS) * 4)

__global__ __launch_bounds__(256)
void attn_kernel(const float* __restrict__ qh, const float* __restrict__ kh,
                 const float* __restrict__ vh, __half* __restrict__ ctx)
{
    extern __shared__ float sm[];
    float* Qs = sm;
    float* Ks = Qs + SS * AROW;
    float* Vs = Ks + SS * AROW;
    float* Ps = Vs + SS * AROW;     // [32][196] : 8 warps x 4 rows

    const int b = blockIdx.x / HH;
    const int h = blockIdx.x % HH;
    const int tid = threadIdx.x;
    const int lane = tid & 31;
    const int w = tid >> 5;

    const size_t base = ((size_t)b * SS) * DD + (size_t)h * DHH;
    for (int idx = tid; idx < SS * DHH; idx += 256) {
        const int r = idx >> 6, d = idx & 63;
        const size_t g = base + (size_t)r * DD + d;
        Qs[r * AROW + d] = qh[g];
        Ks[r * AROW + d] = kh[g];
        Vs[r * AROW + d] = vh[g];
    }
    __syncthreads();

    for (int qb = w; qb < 49; qb += 8) {
        const int q0 = qb * 4;
        float sl[4][7];

        // ---- scores: 4 q rows x lane-strided k, float4 dot ----
        {
            const float4* q0p = (const float4*)&Qs[(q0 + 0) * AROW];
            const float4* q1p = (const float4*)&Qs[(q0 + 1) * AROW];
            const float4* q2p = (const float4*)&Qs[(q0 + 2) * AROW];
            const float4* q3p = (const float4*)&Qs[(q0 + 3) * AROW];
            int slot = 0;
            for (int kk = lane; kk < SS; kk += 32, slot++) {
                const float4* kp = (const float4*)&Ks[kk * AROW];
                float s0 = 0.f, s1 = 0.f, s2 = 0.f, s3 = 0.f;
                #pragma unroll
                for (int d = 0; d < 16; d++) {
                    const float4 kv = kp[d];
                    float4 a;
                    a = q0p[d];
                    s0 = fmaf(a.x, kv.x, fmaf(a.y, kv.y, fmaf(a.z, kv.z, fmaf(a.w, kv.w, s0))));
                    a = q1p[d];
                    s1 = fmaf(a.x, kv.x, fmaf(a.y, kv.y, fmaf(a.z, kv.z, fmaf(a.w, kv.w, s1))));
                    a = q2p[d];
                    s2 = fmaf(a.x, kv.x, fmaf(a.y, kv.y, fmaf(a.z, kv.z, fmaf(a.w, kv.w, s2))));
                    a = q3p[d];
                    s3 = fmaf(a.x, kv.x, fmaf(a.y, kv.y, fmaf(a.z, kv.z, fmaf(a.w, kv.w, s3))));
                }
                sl[0][slot] = s0 * 0.125f;
                sl[1][slot] = s1 * 0.125f;
                sl[2][slot] = s2 * 0.125f;
                sl[3][slot] = s3 * 0.125f;
            }
        }

        // ---- softmax per q row, write P ----
        #pragma unroll
        for (int qi = 0; qi < 4; qi++) {
            float mx = -1e30f;
            {
                int slot = 0;
                for (int kk = lane; kk < SS; kk += 32, slot++)
                    mx = fmaxf(mx, sl[qi][slot]);
            }
            #pragma unroll
            for (int off = 16; off; off >>= 1)
                mx = fmaxf(mx, __shfl_xor_sync(0xffffffffu, mx, off));
            float sum = 0.f;
            {
                int slot = 0;
                for (int kk = lane; kk < SS; kk += 32, slot++) {
                    const float p = __expf(sl[qi][slot] - mx);
                    sl[qi][slot] = p;
                    sum += p;
                }
            }
            #pragma unroll
            for (int off = 16; off; off >>= 1)
                sum += __shfl_xor_sync(0xffffffffu, sum, off);
            const float inv = 1.f / sum;
            {
                int slot = 0;
                for (int kk = lane; kk < SS; kk += 32, slot++)
                    Ps[(w * 4 + qi) * SS + kk] = sl[qi][slot] * inv;
            }
        }
        __syncwarp();

        // ---- PV: V shared across 4 q rows; P read as float4 broadcast ----
        float acc0[4] = {0.f, 0.f, 0.f, 0.f};
        float acc1[4] = {0.f, 0.f, 0.f, 0.f};
        for (int kk = 0; kk < SS; kk += 4) {
            float v0[4], v1[4];
            #pragma unroll
            for (int j = 0; j < 4; j++) {
                v0[j] = Vs[(kk + j) * AROW + lane];
                v1[j] = Vs[(kk + j) * AROW + lane + 32];
            }
            #pragma unroll
            for (int qi = 0; qi < 4; qi++) {
                const float4 p = *(const float4*)&Ps[(w * 4 + qi) * SS + kk];
                acc0[qi] = fmaf(p.x, v0[0], fmaf(p.y, v0[1], fmaf(p.z, v0[2], fmaf(p.w, v0[3], acc0[qi]))));
                acc1[qi] = fmaf(p.x, v1[0], fmaf(p.y, v1[1], fmaf(p.z, v1[2], fmaf(p.w, v1[3], acc1[qi]))));
            }
        }
        #pragma unroll
        for (int qi = 0; qi < 4; qi++) {
            const size_t o = base + (size_t)(q0 + qi) * DD;
            ctx[o + lane]      = __float2half_rn(acc0[qi]);
            ctx[o + lane + 32] = __float2half_rn(acc1[qi]);
        }
        __syncwarp();
    }
}

// ---------------------------------------------------------------------------
// LN / gate kernels
// ---------------------------------------------------------------------------
__device__ __forceinline__ float block_reduce_sum(float v, float* red)
{
    const int lane = threadIdx.x & 31, w = threadIdx.x >> 5;
    #pragma unroll
    for (int off = 16; off; off >>= 1) v += __shfl_xor_sync(0xffffffffu, v, off);
    if (lane == 0) red[w] = v;
    __syncthreads();
    if (w == 0) {
        float t = (lane < 8) ? red[lane] : 0.f;
        #pragma unroll
        for (int off = 4; off; off >>= 1) t += __shfl_xor_sync(0xffffffffu, t, off);
        if (lane == 0) red[0] = t;
    }
    __syncthreads();
    return red[0];
}

__global__ __launch_bounds__(256)
void ln1_kernel(const float* __restrict__ a, const float* __restrict__ b,
                const float* __restrict__ g, const float* __restrict__ beta,
                float* __restrict__ out, __half* __restrict__ oh)
{
    const int m = blockIdx.x;
    __shared__ float buf[DD];
    __shared__ float red1[32];
    __shared__ float red2[32];
    float s = 0.f;
    for (int d = threadIdx.x; d < DD; d += 256) {
        const float v = a[(size_t)m * DD + d] + b[(size_t)m * DD + d];
        buf[d] = v;
        s += v;
    }
    const float mean = block_reduce_sum(s, red1) * (1.f / DD);
    float s2 = 0.f;
    for (int d = threadIdx.x; d < DD; d += 256) {
        const float t = buf[d] - mean;
        s2 += t * t;
    }
    const float var = block_reduce_sum(s2, red2) * (1.f / DD);
    const float rstd = rsqrtf(var + 1e-5f);
    for (int d = threadIdx.x; d < DD; d += 256) {
        const float v = (buf[d] - mean) * rstd * g[d] + beta[d];
        out[(size_t)m * DD + d] = v;
        oh[(size_t)m * DD + d] = __float2half_rn(v);
    }
}

__global__ __launch_bounds__(256)
void gate_kernel(const float* __restrict__ x, const float* __restrict__ Wg,
                 const float* __restrict__ bg, float* __restrict__ gates)
{
    const int m = blockIdx.x;
    const int tid = threadIdx.x, lane = tid & 31, w = tid >> 5;
    float acc[EE] = {0, 0, 0, 0, 0, 0, 0, 0};
    const float* xr = x + (size_t)m * DD;
    for (int d = tid; d < DD; d += 256) {
        const float xv = xr[d];
        #pragma unroll
        for (int e = 0; e < EE; e++) acc[e] = fmaf(xv, Wg[d * EE + e], acc[e]);
    }
    #pragma unroll
    for (int e = 0; e < EE; e++)
        #pragma unroll
        for (int off = 16; off; off >>= 1) acc[e] += __shfl_xor_sync(0xffffffffu, acc[e], off);
    __shared__ float red[8][EE];
    if (lane == 0)
        #pragma unroll
        for (int e = 0; e < EE; e++) red[w][e] = acc[e];
    __syncthreads();
    if (tid == 0) {
        float v[EE];
        float mx = -1e30f;
        for (int e = 0; e < EE; e++) {
            float t = bg[e];
            for (int ww = 0; ww < 8; ww++) t += red[ww][e];
            v[e] = t;
            mx = fmaxf(mx, t);
        }
        float s = 0.f;
        for (int e = 0; e < EE; e++) { v[e] = __expf(v[e] - mx); s += v[e]; }
        const float inv = 1.f / s;
        for (int e = 0; e < EE; e++) gates[(size_t)m * EE + e] = v[e] * inv;
    }
}

__global__ __launch_bounds__(256)
void ln2_kernel(const float* __restrict__ x, const float* __restrict__ gates,
                const float* __restrict__ y, const float* __restrict__ g,
                const float* __restrict__ beta, float* __restrict__ out)
{
    const int m = blockIdx.x;
    __shared__ float buf[DD];
    __shared__ float gl[EE];
    __shared__ float red1[32];
    __shared__ float red2[32];
    if (threadIdx.x < EE) gl[threadIdx.x] = gates[(size_t)m * EE + threadIdx.x];
    __syncthreads();
    float s = 0.f;
    for (int d = threadIdx.x; d < DD; d += 256) {
        float v = x[(size_t)m * DD + d];
        #pragma unroll
        for (int e = 0; e < EE; e++)
            v = fmaf(gl[e], y[((size_t)e * NT + m) * DD + d], v);
        buf[d] = v;
        s += v;
    }
    const float mean = block_reduce_sum(s, red1) * (1.f / DD);
    float s2 = 0.f;
    for (int d = threadIdx.x; d < DD; d += 256) {
        const float t = buf[d] - mean;
        s2 += t * t;
    }
    const float var = block_reduce_sum(s2, red2) * (1.f / DD);
    const float rstd = rsqrtf(var + 1e-5f);
    for (int d = threadIdx.x; d < DD; d += 256)
        out[(size_t)m * DD + d] = (buf[d] - mean) * rstd * g[d] + beta[d];
}

// ---------------------------------------------------------------------------
// launch
// ---------------------------------------------------------------------------
extern "C" void kernel_launch(void* const* d_in, const int* in_sizes, int n_in,
                              void* d_out, int out_size)
{
    const float* q    = (const float*)d_in[0];
    const float* k    = (const float*)d_in[1];
    const float* v    = (const float*)d_in[2];
    const float* Wq   = (const float*)d_in[3];
    const float* bq   = (const float*)d_in[4];
    const float* Wk   = (const float*)d_in[5];
    const float* bk   = (const float*)d_in[6];
    const float* Wv   = (const float*)d_in[7];
    const float* bv   = (const float*)d_in[8];
    const float* Wo   = (const float*)d_in[9];
    const float* bo   = (const float*)d_in[10];
    const float* ln1g = (const float*)d_in[11];
    const float* ln1b = (const float*)d_in[12];
    const float* ln2g = (const float*)d_in[13];
    const float* ln2b = (const float*)d_in[14];
    const float* Wg   = (const float*)d_in[15];
    const float* bg   = (const float*)d_in[16];
    const float* W1   = (const float*)d_in[17];
    const float* b1   = (const float*)d_in[18];
    const float* W2   = (const float*)d_in[19];
    const float* b2   = (const float*)d_in[20];
    float* out = (float*)d_out;

    __half *qa, *ka, *va, *ctx, *xh, *hact;
    __half *WqT, *WkT, *WvT, *WoT, *W1T, *W2T;
    float *qh, *kh, *vh, *attn, *x, *gates, *y;
    cudaGetSymbolAddress((void**)&qa, g_qa);
    cudaGetSymbolAddress((void**)&ka, g_ka);
    cudaGetSymbolAddress((void**)&va, g_va);
    cudaGetSymbolAddress((void**)&qh, g_qh);
    cudaGetSymbolAddress((void**)&kh, g_kh);
    cudaGetSymbolAddress((void**)&vh, g_vh);
    cudaGetSymbolAddress((void**)&ctx, g_ctx);
    cudaGetSymbolAddress((void**)&attn, g_attn);
    cudaGetSymbolAddress((void**)&x, g_x);
    cudaGetSymbolAddress((void**)&xh, g_xh);
    cudaGetSymbolAddress((void**)&gates, g_gates);
    cudaGetSymbolAddress((void**)&hact, g_hact);
    cudaGetSymbolAddress((void**)&y, g_y);
    cudaGetSymbolAddress((void**)&WqT, g_WqT);
    cudaGetSymbolAddress((void**)&WkT, g_WkT);
    cudaGetSymbolAddress((void**)&WvT, g_WvT);
    cudaGetSymbolAddress((void**)&WoT, g_WoT);
    cudaGetSymbolAddress((void**)&W1T, g_W1T);
    cudaGetSymbolAddress((void**)&W2T, g_W2T);

    cudaFuncSetAttribute(attn_kernel, cudaFuncAttributeMaxDynamicSharedMemorySize, ATTN_SMEM);
    cudaFuncSetAttribute(gemm_f16<0>, cudaFuncAttributeMaxDynamicSharedMemorySize, GEMM_SMEM);
    cudaFuncSetAttribute(gemm_f16<1>, cudaFuncAttributeMaxDynamicSharedMemorySize, GEMM_SMEM);

    const dim3 blk(256);
    const long long nAct = (long long)NT * DD;

    // 1) convert inputs to fp16
    convert_h_kernel<<<1024, blk>>>(q, qa, nAct);
    convert_h_kernel<<<1024, blk>>>(k, ka, nAct);
    convert_h_kernel<<<1024, blk>>>(v, va, nAct);

    // 2) transpose + convert weights ([K,N] -> [N,K] fp16)
    transpose_h_kernel<<<dim3(DD/32, DD/32, 1), dim3(32, 8)>>>(Wq, WqT, DD, DD);
    transpose_h_kernel<<<dim3(DD/32, DD/32, 1), dim3(32, 8)>>>(Wk, WkT, DD, DD);
    transpose_h_kernel<<<dim3(DD/32, DD/32, 1), dim3(32, 8)>>>(Wv, WvT, DD, DD);
    transpose_h_kernel<<<dim3(DD/32, DD/32, 1), dim3(32, 8)>>>(Wo, WoT, DD, DD);
    transpose_h_kernel<<<dim3(FF/32, DD/32, EE), dim3(32, 8)>>>(W1, W1T, DD, FF);
    transpose_h_kernel<<<dim3(DD/32, FF/32, EE), dim3(32, 8)>>>(W2, W2T, FF, DD);

    // 3) QKV projections
    gemm_f16<0><<<dim3(DD/GBN, NT/GBM, 1), blk, GEMM_SMEM>>>(
        qa, WqT, bq, qh, nullptr, DD, DD, 0, 0, 0, 0);
    gemm_f16<0><<<dim3(DD/GBN, NT/GBM, 1), blk, GEMM_SMEM>>>(
        ka, WkT, bk, kh, nullptr, DD, DD, 0, 0, 0, 0);
    gemm_f16<0><<<dim3(DD/GBN, NT/GBM, 1), blk, GEMM_SMEM>>>(
        va, WvT, bv, vh, nullptr, DD, DD, 0, 0, 0, 0);

    // 4) attention
    attn_kernel<<<BB * HH, blk, ATTN_SMEM>>>(qh, kh, vh, ctx);

    // 5) output projection
    gemm_f16<0><<<dim3(DD/GBN, NT/GBM, 1), blk, GEMM_SMEM>>>(
        ctx, WoT, bo, attn, nullptr, DD, DD, 0, 0, 0, 0);

    // 6) LN1 + fp16 copy
    ln1_kernel<<<NT, blk>>>(q, attn, ln1g, ln1b, x, xh);

    // 7) gates
    gate_kernel<<<NT, blk>>>(x, Wg, bg, gates);

    // 8) MoE FFN1 (gelu -> fp16)
    gemm_f16<1><<<dim3(FF/GBN, NT/GBM, EE), blk, GEMM_SMEM>>>(
        xh, W1T, b1, nullptr, hact, DD, FF,
        0, (long long)FF * DD, (long long)FF, (long long)NT * FF);

    // 9) MoE FFN2
    gemm_f16<0><<<dim3(DD/GBN, NT/GBM, EE), blk, GEMM_SMEM>>>(
        hact, W2T, b2, y, nullptr, FF, DD,
        (long long)NT * FF, (long long)DD * FF, (long long)DD, (long long)NT * DD);

    // 10) LN2
    ln2_kernel<<<NT, blk>>>(x, gates, y, ln2g, ln2b, out);

    (void)in_sizes; (void)n_in; (void)out_size;
}

// round 5
// speedup vs baseline: 6.2677x; 1.0829x over previous
#include <cuda_runtime.h>
#include <cuda_fp16.h>
#include <math.h>
#include <stdint.h>

// Problem constants
#define BB 32
#define SS 196
#define DD 768
#define HH 12
#define DHH 64
#define EE 8
#define FF 3072
#define NT (BB*SS)          // 6272 tokens

// ---------------------------------------------------------------------------
// helpers
// ---------------------------------------------------------------------------
__device__ __forceinline__ uint32_t smem_u32(const void* p) {
    uint32_t a;
    asm("{ .reg .u64 t; cvta.to.shared.u64 t, %1; cvt.u32.u64 %0, t; }"
        : "=r"(a) : "l"(p));
    return a;
}

__device__ __forceinline__ void cpa16(uint32_t s, const void* g) {
    asm volatile("cp.async.cg.shared.global [%0], [%1], 16;" :: "r"(s), "l"(g));
}
__device__ __forceinline__ void cpa_commit() { asm volatile("cp.async.commit_group;"); }
template<int N> __device__ __forceinline__ void cpa_wait() {
    asm volatile("cp.async.wait_group %0;" :: "n"(N));
}

#define LDMX4(r, addr) \
    asm volatile("ldmatrix.sync.aligned.m8n8.x4.shared.b16 {%0,%1,%2,%3}, [%4];" \
        : "=r"((r)[0]), "=r"((r)[1]), "=r"((r)[2]), "=r"((r)[3]) : "r"(addr))

__device__ __forceinline__ void mma16816(float* d, const uint32_t* a, const uint32_t* b) {
    asm volatile("mma.sync.aligned.m16n8k16.row.col.f32.f16.f16.f32 "
        "{%0,%1,%2,%3}, {%4,%5,%6,%7}, {%8,%9}, {%0,%1,%2,%3};"
        : "+f"(d[0]), "+f"(d[1]), "+f"(d[2]), "+f"(d[3])
        : "r"(a[0]), "r"(a[1]), "r"(a[2]), "r"(a[3]), "r"(b[0]), "r"(b[1]));
}

__device__ __forceinline__ float gelu_exact(float v) {
    return 0.5f * v * (1.f + erff(v * 0.70710678118654752f));
}

// ---------------------------------------------------------------------------
// device scratch
// ---------------------------------------------------------------------------
__device__ __half g_qkva[(size_t)3*NT*DD];        // fp16 q,k,v inputs (contig)
__device__ float  g_qkvh[(size_t)3*NT*DD];        // projected q,k,v (fp32)
__device__ __half g_ctx[(size_t)NT*DD];
__device__ float  g_attn[(size_t)NT*DD];
__device__ float  g_x[(size_t)NT*DD];
__device__ __half g_xh[(size_t)NT*DD];
__device__ float  g_gates[(size_t)NT*EE];
__device__ __half g_hact[(size_t)EE*NT*FF];       // gated gelu activations
__device__ float  g_moe[(size_t)NT*DD];           // sum_e gated expert outputs
__device__ __half g_WqkvT[(size_t)3*DD*DD];
__device__ float  g_bqkv[(size_t)3*DD];
__device__ __half g_WoT[(size_t)DD*DD];
__device__ __half g_W1T[(size_t)EE*FF*DD];
__device__ __half g_W2T[(size_t)EE*DD*FF];

// ---------------------------------------------------------------------------
// conversion kernels
// ---------------------------------------------------------------------------
__global__ __launch_bounds__(256)
void convert_h_kernel(const float* __restrict__ in, __half* __restrict__ o, long long n)
{
    long long i = (long long)blockIdx.x * blockDim.x + threadIdx.x;
    const long long stride = (long long)gridDim.x * blockDim.x;
    for (; i < n; i += stride) o[i] = __float2half_rn(in[i]);
}

__global__ __launch_bounds__(256)
void concat3_kernel(const float* __restrict__ a, const float* __restrict__ b,
                    const float* __restrict__ c, float* __restrict__ o)
{
    const int i = blockIdx.x * blockDim.x + threadIdx.x;
    if (i < DD) { o[i] = a[i]; o[DD + i] = b[i]; o[2 * DD + i] = c[i]; }
}

// in: [batch, K, N] fp32  ->  out: [batch, N, K] fp16
__global__ __launch_bounds__(256)
void transpose_h_kernel(const float* __restrict__ in, __half* __restrict__ o, int K, int N)
{
    __shared__ float t[32][33];
    const size_t bz = blockIdx.z;
    const float* ip = in + bz * (size_t)K * N;
    __half* op = o + bz * (size_t)K * N;
    const int k0 = blockIdx.y * 32, n0 = blockIdx.x * 32;
    const int tx = threadIdx.x, ty = threadIdx.y;
    #pragma unroll
    for (int j = 0; j < 4; j++)
        t[ty + j * 8][tx] = ip[(size_t)(k0 + ty + j * 8) * N + n0 + tx];
    __syncthreads();
    #pragma unroll
    for (int j = 0; j < 4; j++)
        op[(size_t)(n0 + ty + j * 8) * K + k0 + tx] = __float2half_rn(t[tx][ty + j * 8]);
}

// ---------------------------------------------------------------------------
// HMMA fp16 GEMM: C[M,N] = A[M,K] @ B[N,K]^T (+ bias)
// BM=128 BN=256 BK=64, 256 threads, warp tile 64x64, 3-stage cp.async.
// smem rows 144B (64 halfs + pad) -> ldmatrix conflict-free.
// EPI 0: +bias -> fp32.   EPI 1: gate[m,e]*gelu(+bias) -> fp16.
// ---------------------------------------------------------------------------
#define GBM 128
#define GBN 256
#define GBK 64
#define RB 144
#define TILE_A (128 * RB)                  // 18432
#define TILE_B (256 * RB)                  // 36864
#define STAGE_BYTES (TILE_A + TILE_B)      // 55296
#define NSTAGE 3
#define GEMM_SMEM (NSTAGE * STAGE_BYTES)   // 165888

template<int EPI>
__global__ __launch_bounds__(256, 1)
void gemm_f16(const __half* __restrict__ A, const __half* __restrict__ B,
              const float* __restrict__ bias, const float* __restrict__ gates,
              float* __restrict__ C, __half* __restrict__ Ch,
              int K, int ldC,
              long long strA, long long strB, long long strBias, long long strC)
{
    extern __shared__ char smem[];
    const uint32_t smem_base = smem_u32(smem);

    const int tid = threadIdx.x;
    const int lane = tid & 31;
    const int wid = tid >> 5;
    const int wm = wid & 1;
    const int wn = wid >> 1;

    const long long bz = blockIdx.z;
    A += bz * strA;
    B += bz * strB;
    bias += bz * strBias;

    const int m0 = blockIdx.y * GBM;
    const int n0 = blockIdx.x * GBN;
    const int NC = K / GBK;

    auto load_stage = [&](int kc, int st) {
        const uint32_t sb = smem_base + st * STAGE_BYTES;
        const long long k0 = (long long)kc * GBK;
        #pragma unroll
        for (int i = tid; i < 1024; i += 256) {           // A: 128 rows x 8 vec16
            const int r = i >> 3;
            const int c = (i & 7) * 8;
            cpa16(sb + r * RB + c * 2, A + (size_t)(m0 + r) * K + k0 + c);
        }
        #pragma unroll
        for (int i = tid; i < 2048; i += 256) {           // B: 256 rows x 8 vec16
            const int r = i >> 3;
            const int c = (i & 7) * 8;
            cpa16(sb + TILE_A + r * RB + c * 2, B + (size_t)(n0 + r) * K + k0 + c);
        }
        cpa_commit();
    };

    load_stage(0, 0);
    if (NC > 1) load_stage(1, 1);

    float acc[4][8][4];
    #pragma unroll
    for (int i = 0; i < 4; i++)
        #pragma unroll
        for (int j = 0; j < 8; j++)
            #pragma unroll
            for (int r = 0; r < 4; r++) acc[i][j][r] = 0.f;

    const int a_row_in16 = lane & 15;
    const int a_col8 = (lane >> 4) * 8;
    const int b_row_in16 = ((lane >> 4) << 3) + (lane & 7);
    const int b_col8 = ((lane >> 3) & 1) * 8;

    for (int kc = 0; kc < NC; kc++) {
        cpa_wait<NSTAGE - 2>();
        __syncthreads();

        const uint32_t sa = smem_base + (kc % NSTAGE) * STAGE_BYTES;
        const uint32_t sbB = sa + TILE_A;

        #pragma unroll
        for (int ks = 0; ks < 4; ks++) {
            uint32_t af[4][4];
            uint32_t bf[8][2];
            #pragma unroll
            for (int ms = 0; ms < 4; ms++) {
                const uint32_t addr = sa
                    + (uint32_t)(wm * 64 + ms * 16 + a_row_in16) * RB
                    + (uint32_t)(a_col8 + ks * 16) * 2;
                LDMX4(af[ms], addr);
            }
            #pragma unroll
            for (int bs = 0; bs < 4; bs++) {
                uint32_t r[4];
                const uint32_t addr = sbB
                    + (uint32_t)(wn * 64 + bs * 16 + b_row_in16) * RB
                    + (uint32_t)(b_col8 + ks * 16) * 2;
                LDMX4(r, addr);
                bf[2 * bs][0] = r[0]; bf[2 * bs][1] = r[1];
                bf[2 * bs + 1][0] = r[2]; bf[2 * bs + 1][1] = r[3];
            }
            #pragma unroll
            for (int ms = 0; ms < 4; ms++)
                #pragma unroll
                for (int ns = 0; ns < 8; ns++)
                    mma16816(acc[ms][ns], af[ms], bf[ns]);
        }

        if (kc + NSTAGE - 1 < NC)
            load_stage(kc + NSTAGE - 1, (kc + NSTAGE - 1) % NSTAGE);
    }

    // ---- epilogue ----
    const int row_g = lane >> 2;
    const int col_g = (lane & 3) * 2;
    #pragma unroll
    for (int ms = 0; ms < 4; ms++) {
        const int mA = m0 + wm * 64 + ms * 16 + row_g;
        const int mB = mA + 8;
        float gA = 1.f, gB = 1.f;
        if (EPI == 1) {
            gA = gates[(size_t)mA * EE + bz];
            gB = gates[(size_t)mB * EE + bz];
        }
        #pragma unroll
        for (int ns = 0; ns < 8; ns++) {
            const int n = n0 + wn * 64 + ns * 8 + col_g;
            const float b0 = bias[n], b1 = bias[n + 1];
            if (EPI == 0) {
                float* Cb = C + bz * strC;
                float2 o0, o1;
                o0.x = acc[ms][ns][0] + b0;  o0.y = acc[ms][ns][1] + b1;
                o1.x = acc[ms][ns][2] + b0;  o1.y = acc[ms][ns][3] + b1;
                *(float2*)&Cb[(size_t)mA * ldC + n] = o0;
                *(float2*)&Cb[(size_t)mB * ldC + n] = o1;
            } else {
                __half* Cb = Ch + bz * strC;
                __half2 o0, o1;
                o0.x = __float2half_rn(gA * gelu_exact(acc[ms][ns][0] + b0));
                o0.y = __float2half_rn(gA * gelu_exact(acc[ms][ns][1] + b1));
                o1.x = __float2half_rn(gB * gelu_exact(acc[ms][ns][2] + b0));
                o1.y = __float2half_rn(gB * gelu_exact(acc[ms][ns][3] + b1));
                *(__half2*)&Cb[(size_t)mA * ldC + n] = o0;
                *(__half2*)&Cb[(size_t)mB * ldC + n] = o1;
            }
        }
    }
}

// ---------------------------------------------------------------------------
// MoE FFN2: moe[M,DD] = sum_e hact[e][M,FF] @ W2T[e][DD,FF]^T
// (gates already folded into hact; expert biases added in LN2)
// Flattened K loop over 8 experts x 48 chunks.
// ---------------------------------------------------------------------------
__global__ __launch_bounds__(256, 1)
void gemm_moe(const __half* __restrict__ Hact, const __half* __restrict__ W2T,
              float* __restrict__ Moe)
{
    extern __shared__ char smem[];
    const uint32_t smem_base = smem_u32(smem);

    const int tid = threadIdx.x;
    const int lane = tid & 31;
    const int wid = tid >> 5;
    const int wm = wid & 1;
    const int wn = wid >> 1;

    const int m0 = blockIdx.y * GBM;
    const int n0 = blockIdx.x * GBN;
    const int CPE = FF / GBK;               // 48 chunks per expert
    const int NC = EE * CPE;                // 384

    auto load_stage = [&](int kc, int st) {
        const uint32_t sb = smem_base + st * STAGE_BYTES;
        const int e = kc / CPE;
        const long long k0 = (long long)(kc - e * CPE) * GBK;
        const __half* Ab = Hact + ((size_t)e * NT + m0) * FF + k0;
        const __half* Bb = W2T + ((size_t)e * DD + n0) * FF + k0;
        #pragma unroll
        for (int i = tid; i < 1024; i += 256) {
            const int r = i >> 3;
            const int c = (i & 7) * 8;
            cpa16(sb + r * RB + c * 2, Ab + (size_t)r * FF + c);
        }
        #pragma unroll
        for (int i = tid; i < 2048; i += 256) {
            const int r = i >> 3;
            const int c = (i & 7) * 8;
            cpa16(sb + TILE_A + r * RB + c * 2, Bb + (size_t)r * FF + c);
        }
        cpa_commit();
    };

    load_stage(0, 0);
    load_stage(1, 1);

    float acc[4][8][4];
    #pragma unroll
    for (int i = 0; i < 4; i++)
        #pragma unroll
        for (int j = 0; j < 8; j++)
            #pragma unroll
            for (int r = 0; r < 4; r++) acc[i][j][r] = 0.f;

    const int a_row_in16 = lane & 15;
    const int a_col8 = (lane >> 4) * 8;
    const int b_row_in16 = ((lane >> 4) << 3) + (lane & 7);
    const int b_col8 = ((lane >> 3) & 1) * 8;

    for (int kc = 0; kc < NC; kc++) {
        cpa_wait<NSTAGE - 2>();
        __syncthreads();

        const uint32_t sa = smem_base + (kc % NSTAGE) * STAGE_BYTES;
        const uint32_t sbB = sa + TILE_A;

        #pragma unroll
        for (int ks = 0; ks < 4; ks++) {
            uint32_t af[4][4];
            uint32_t bf[8][2];
            #pragma unroll
            for (int ms = 0; ms < 4; ms++) {
                const uint32_t addr = sa
                    + (uint32_t)(wm * 64 + ms * 16 + a_row_in16) * RB
                    + (uint32_t)(a_col8 + ks * 16) * 2;
                LDMX4(af[ms], addr);
            }
            #pragma unroll
            for (int bs = 0; bs < 4; bs++) {
                uint32_t r[4];
                const uint32_t addr = sbB
                    + (uint32_t)(wn * 64 + bs * 16 + b_row_in16) * RB
                    + (uint32_t)(b_col8 + ks * 16) * 2;
                LDMX4(r, addr);
                bf[2 * bs][0] = r[0]; bf[2 * bs][1] = r[1];
                bf[2 * bs + 1][0] = r[2]; bf[2 * bs + 1][1] = r[3];
            }
            #pragma unroll
            for (int ms = 0; ms < 4; ms++)
                #pragma unroll
                for (int ns = 0; ns < 8; ns++)
                    mma16816(acc[ms][ns], af[ms], bf[ns]);
        }

        if (kc + NSTAGE - 1 < NC)
            load_stage(kc + NSTAGE - 1, (kc + NSTAGE - 1) % NSTAGE);
    }

    const int row_g = lane >> 2;
    const int col_g = (lane & 3) * 2;
    #pragma unroll
    for (int ms = 0; ms < 4; ms++) {
        const int mA = m0 + wm * 64 + ms * 16 + row_g;
        const int mB = mA + 8;
        #pragma unroll
        for (int ns = 0; ns < 8; ns++) {
            const int n = n0 + wn * 64 + ns * 8 + col_g;
            float2 o0, o1;
            o0.x = acc[ms][ns][0];  o0.y = acc[ms][ns][1];
            o1.x = acc[ms][ns][2];  o1.y = acc[ms][ns][3];
            *(float2*)&Moe[(size_t)mA * DD + n] = o0;
            *(float2*)&Moe[(size_t)mB * DD + n] = o1;
        }
    }
}

// ---------------------------------------------------------------------------
// attention: per (b,h) block, 4-query blocking + float4 LDS, fp16 ctx out
// ---------------------------------------------------------------------------
#define AROW 68
#define ATTN_SMEM ((3 * SS * AROW + 32 * SS) * 4)

__global__ __launch_bounds__(256)
void attn_kernel(const float* __restrict__ qh, const float* __restrict__ kh,
                 const float* __restrict__ vh, __half* __restrict__ ctx)
{
    extern __shared__ float sm[];
    float* Qs = sm;
    float* Ks = Qs + SS * AROW;
    float* Vs = Ks + SS * AROW;
    float* Ps = Vs + SS * AROW;

    const int b = blockIdx.x / HH;
    const int h = blockIdx.x % HH;
    const int tid = threadIdx.x;
    const int lane = tid & 31;
    const int w = tid >> 5;

    const size_t base = ((size_t)b * SS) * DD + (size_t)h * DHH;
    for (int idx = tid; idx < SS * DHH; idx += 256) {
        const int r = idx >> 6, d = idx & 63;
        const size_t g = base + (size_t)r * DD + d;
        Qs[r * AROW + d] = qh[g];
        Ks[r * AROW + d] = kh[g];
        Vs[r * AROW + d] = vh[g];
    }
    __syncthreads();

    for (int qb = w; qb < 49; qb += 8) {
        const int q0 = qb * 4;
        float sl[4][7];

        {
            const float4* q0p = (const float4*)&Qs[(q0 + 0) * AROW];
            const float4* q1p = (const float4*)&Qs[(q0 + 1) * AROW];
            const float4* q2p = (const float4*)&Qs[(q0 + 2) * AROW];
            const float4* q3p = (const float4*)&Qs[(q0 + 3) * AROW];
            int slot = 0;
            for (int kk = lane; kk < SS; kk += 32, slot++) {
                const float4* kp = (const float4*)&Ks[kk * AROW];
                float s0 = 0.f, s1 = 0.f, s2 = 0.f, s3 = 0.f;
                #pragma unroll
                for (int d = 0; d < 16; d++) {
                    const float4 kv = kp[d];
                    float4 a;
                    a = q0p[d];
                    s0 = fmaf(a.x, kv.x, fmaf(a.y, kv.y, fmaf(a.z, kv.z, fmaf(a.w, kv.w, s0))));
                    a = q1p[d];
                    s1 = fmaf(a.x, kv.x, fmaf(a.y, kv.y, fmaf(a.z, kv.z, fmaf(a.w, kv.w, s1))));
                    a = q2p[d];
                    s2 = fmaf(a.x, kv.x, fmaf(a.y, kv.y, fmaf(a.z, kv.z, fmaf(a.w, kv.w, s2))));
                    a = q3p[d];
                    s3 = fmaf(a.x, kv.x, fmaf(a.y, kv.y, fmaf(a.z, kv.z, fmaf(a.w, kv.w, s3))));
                }
                sl[0][slot] = s0 * 0.125f;
                sl[1][slot] = s1 * 0.125f;
                sl[2][slot] = s2 * 0.125f;
                sl[3][slot] = s3 * 0.125f;
            }
        }

        #pragma unroll
        for (int qi = 0; qi < 4; qi++) {
            float mx = -1e30f;
            {
                int slot = 0;
                for (int kk = lane; kk < SS; kk += 32, slot++)
                    mx = fmaxf(mx, sl[qi][slot]);
            }
            #pragma unroll
            for (int off = 16; off; off >>= 1)
                mx = fmaxf(mx, __shfl_xor_sync(0xffffffffu, mx, off));
            float sum = 0.f;
            {
                int slot = 0;
                for (int kk = lane; kk < SS; kk += 32, slot++) {
                    const float p = __expf(sl[qi][slot] - mx);
                    sl[qi][slot] = p;
                    sum += p;
                }
            }
            #pragma unroll
            for (int off = 16; off; off >>= 1)
                sum += __shfl_xor_sync(0xffffffffu, sum, off);
            const float inv = 1.f / sum;
            {
                int slot = 0;
                for (int kk = lane; kk < SS; kk += 32, slot++)
                    Ps[(w * 4 + qi) * SS + kk] = sl[qi][slot] * inv;
            }
        }
        __syncwarp();

        float acc0[4] = {0.f, 0.f, 0.f, 0.f};
        float acc1[4] = {0.f, 0.f, 0.f, 0.f};
        for (int kk = 0; kk < SS; kk += 4) {
            float v0[4], v1[4];
            #pragma unroll
            for (int j = 0; j < 4; j++) {
                v0[j] = Vs[(kk + j) * AROW + lane];
                v1[j] = Vs[(kk + j) * AROW + lane + 32];
            }
            #pragma unroll
            for (int qi = 0; qi < 4; qi++) {
                const float4 p = *(const float4*)&Ps[(w * 4 + qi) * SS + kk];
                acc0[qi] = fmaf(p.x, v0[0], fmaf(p.y, v0[1], fmaf(p.z, v0[2], fmaf(p.w, v0[3], acc0[qi]))));
                acc1[qi] = fmaf(p.x, v1[0], fmaf(p.y, v1[1], fmaf(p.z, v1[2], fmaf(p.w, v1[3], acc1[qi]))));
            }
        }
        #pragma unroll
        for (int qi = 0; qi < 4; qi++) {
            const size_t o = base + (size_t)(q0 + qi) * DD;
            ctx[o + lane]      = __float2half_rn(acc0[qi]);
            ctx[o + lane + 32] = __float2half_rn(acc1[qi]);
        }
        __syncwarp();
    }
}

// ---------------------------------------------------------------------------
// LN / gate kernels
// ---------------------------------------------------------------------------
__device__ __forceinline__ float block_reduce_sum(float v, float* red)
{
    const int lane = threadIdx.x & 31, w = threadIdx.x >> 5;
    #pragma unroll
    for (int off = 16; off; off >>= 1) v += __shfl_xor_sync(0xffffffffu, v, off);
    if (lane == 0) red[w] = v;
    __syncthreads();
    if (w == 0) {
        float t = (lane < 8) ? red[lane] : 0.f;
        #pragma unroll
        for (int off = 4; off; off >>= 1) t += __shfl_xor_sync(0xffffffffu, t, off);
        if (lane == 0) red[0] = t;
    }
    __syncthreads();
    return red[0];
}

__global__ __launch_bounds__(256)
void ln1_kernel(const float* __restrict__ a, const float* __restrict__ b,
                const float* __restrict__ g, const float* __restrict__ beta,
                float* __restrict__ out, __half* __restrict__ oh)
{
    const int m = blockIdx.x;
    __shared__ float buf[DD];
    __shared__ float red1[32];
    __shared__ float red2[32];
    float s = 0.f;
    for (int d = threadIdx.x; d < DD; d += 256) {
        const float v = a[(size_t)m * DD + d] + b[(size_t)m * DD + d];
        buf[d] = v;
        s += v;
    }
    const float mean = block_reduce_sum(s, red1) * (1.f / DD);
    float s2 = 0.f;
    for (int d = threadIdx.x; d < DD; d += 256) {
        const float t = buf[d] - mean;
        s2 += t * t;
    }
    const float var = block_reduce_sum(s2, red2) * (1.f / DD);
    const float rstd = rsqrtf(var + 1e-5f);
    for (int d = threadIdx.x; d < DD; d += 256) {
        const float v = (buf[d] - mean) * rstd * g[d] + beta[d];
        out[(size_t)m * DD + d] = v;
        oh[(size_t)m * DD + d] = __float2half_rn(v);
    }
}

__global__ __launch_bounds__(256)
void gate_kernel(const float* __restrict__ x, const float* __restrict__ Wg,
                 const float* __restrict__ bg, float* __restrict__ gates)
{
    const int m = blockIdx.x;
    const int tid = threadIdx.x, lane = tid & 31, w = tid >> 5;
    float acc[EE] = {0, 0, 0, 0, 0, 0, 0, 0};
    const float* xr = x + (size_t)m * DD;
    for (int d = tid; d < DD; d += 256) {
        const float xv = xr[d];
        #pragma unroll
        for (int e = 0; e < EE; e++) acc[e] = fmaf(xv, Wg[d * EE + e], acc[e]);
    }
    #pragma unroll
    for (int e = 0; e < EE; e++)
        #pragma unroll
        for (int off = 16; off; off >>= 1) acc[e] += __shfl_xor_sync(0xffffffffu, acc[e], off);
    __shared__ float red[8][EE];
    if (lane == 0)
        #pragma unroll
        for (int e = 0; e < EE; e++) red[w][e] = acc[e];
    __syncthreads();
    if (tid == 0) {
        float v[EE];
        float mx = -1e30f;
        for (int e = 0; e < EE; e++) {
            float t = bg[e];
            for (int ww = 0; ww < 8; ww++) t += red[ww][e];
            v[e] = t;
            mx = fmaxf(mx, t);
        }
        float s = 0.f;
        for (int e = 0; e < EE; e++) { v[e] = __expf(v[e] - mx); s += v[e]; }
        const float inv = 1.f / s;
        for (int e = 0; e < EE; e++) gates[(size_t)m * EE + e] = v[e] * inv;
    }
}

// LN2: out = LN(x + moe + sum_e gates[e]*b2[e])
__global__ __launch_bounds__(256)
void ln2_kernel(const float* __restrict__ x, const float* __restrict__ moe,
                const float* __restrict__ gates, const float* __restrict__ b2,
                const float* __restrict__ g, const float* __restrict__ beta,
                float* __restrict__ out)
{
    const int m = blockIdx.x;
    __shared__ float buf[DD];
    __shared__ float gl[EE];
    __shared__ float red1[32];
    __shared__ float red2[32];
    if (threadIdx.x < EE) gl[threadIdx.x] = gates[(size_t)m * EE + threadIdx.x];
    __syncthreads();
    float s = 0.f;
    for (int d = threadIdx.x; d < DD; d += 256) {
        float bsum = 0.f;
        #pragma unroll
        for (int e = 0; e < EE; e++)
            bsum = fmaf(gl[e], b2[(size_t)e * DD + d], bsum);
        const float v = x[(size_t)m * DD + d] + moe[(size_t)m * DD + d] + bsum;
        buf[d] = v;
        s += v;
    }
    const float mean = block_reduce_sum(s, red1) * (1.f / DD);
    float s2 = 0.f;
    for (int d = threadIdx.x; d < DD; d += 256) {
        const float t = buf[d] - mean;
        s2 += t * t;
    }
    const float var = block_reduce_sum(s2, red2) * (1.f / DD);
    const float rstd = rsqrtf(var + 1e-5f);
    for (int d = threadIdx.x; d < DD; d += 256)
        out[(size_t)m * DD + d] = (buf[d] - mean) * rstd * g[d] + beta[d];
}

// ---------------------------------------------------------------------------
// launch
// ---------------------------------------------------------------------------
extern "C" void kernel_launch(void* const* d_in, const int* in_sizes, int n_in,
                              void* d_out, int out_size)
{
    const float* q    = (const float*)d_in[0];
    const float* k    = (const float*)d_in[1];
    const float* v    = (const float*)d_in[2];
    const float* Wq   = (const float*)d_in[3];
    const float* bq   = (const float*)d_in[4];
    const float* Wk   = (const float*)d_in[5];
    const float* bk   = (const float*)d_in[6];
    const float* Wv   = (const float*)d_in[7];
    const float* bv   = (const float*)d_in[8];
    const float* Wo   = (const float*)d_in[9];
    const float* bo   = (const float*)d_in[10];
    const float* ln1g = (const float*)d_in[11];
    const float* ln1b = (const float*)d_in[12];
    const float* ln2g = (const float*)d_in[13];
    const float* ln2b = (const float*)d_in[14];
    const float* Wg   = (const float*)d_in[15];
    const float* bg   = (const float*)d_in[16];
    const float* W1   = (const float*)d_in[17];
    const float* b1   = (const float*)d_in[18];
    const float* W2   = (const float*)d_in[19];
    const float* b2   = (const float*)d_in[20];
    float* out = (float*)d_out;

    __half *qkva, *ctx, *xh, *hact, *WqkvT, *WoT, *W1T, *W2T;
    float *qkvh, *attn, *x, *gates, *moe, *bqkv;
    cudaGetSymbolAddress((void**)&qkva, g_qkva);
    cudaGetSymbolAddress((void**)&qkvh, g_qkvh);
    cudaGetSymbolAddress((void**)&ctx, g_ctx);
    cudaGetSymbolAddress((void**)&attn, g_attn);
    cudaGetSymbolAddress((void**)&x, g_x);
    cudaGetSymbolAddress((void**)&xh, g_xh);
    cudaGetSymbolAddress((void**)&gates, g_gates);
    cudaGetSymbolAddress((void**)&hact, g_hact);
    cudaGetSymbolAddress((void**)&moe, g_moe);
    cudaGetSymbolAddress((void**)&WqkvT, g_WqkvT);
    cudaGetSymbolAddress((void**)&bqkv, g_bqkv);
    cudaGetSymbolAddress((void**)&WoT, g_WoT);
    cudaGetSymbolAddress((void**)&W1T, g_W1T);
    cudaGetSymbolAddress((void**)&W2T, g_W2T);

    cudaFuncSetAttribute(attn_kernel, cudaFuncAttributeMaxDynamicSharedMemorySize, ATTN_SMEM);
    cudaFuncSetAttribute(gemm_f16<0>, cudaFuncAttributeMaxDynamicSharedMemorySize, GEMM_SMEM);
    cudaFuncSetAttribute(gemm_f16<1>, cudaFuncAttributeMaxDynamicSharedMemorySize, GEMM_SMEM);
    cudaFuncSetAttribute(gemm_moe,   cudaFuncAttributeMaxDynamicSharedMemorySize, GEMM_SMEM);

    const dim3 blk(256);
    const long long nAct = (long long)NT * DD;

    // 1) convert inputs to fp16 (contiguous q|k|v)
    convert_h_kernel<<<1024, blk>>>(q, qkva, nAct);
    convert_h_kernel<<<1024, blk>>>(k, qkva + nAct, nAct);
    convert_h_kernel<<<1024, blk>>>(v, qkva + 2 * nAct, nAct);

    // 2) transpose + convert weights
    transpose_h_kernel<<<dim3(DD/32, DD/32, 1), dim3(32, 8)>>>(Wq, WqkvT, DD, DD);
    transpose_h_kernel<<<dim3(DD/32, DD/32, 1), dim3(32, 8)>>>(Wk, WqkvT + (size_t)DD*DD, DD, DD);
    transpose_h_kernel<<<dim3(DD/32, DD/32, 1), dim3(32, 8)>>>(Wv, WqkvT + 2*(size_t)DD*DD, DD, DD);
    transpose_h_kernel<<<dim3(DD/32, DD/32, 1), dim3(32, 8)>>>(Wo, WoT, DD, DD);
    transpose_h_kernel<<<dim3(FF/32, DD/32, EE), dim3(32, 8)>>>(W1, W1T, DD, FF);
    transpose_h_kernel<<<dim3(DD/32, FF/32, EE), dim3(32, 8)>>>(W2, W2T, FF, DD);
    concat3_kernel<<<3, blk>>>(bq, bk, bv, bqkv);

    // 3) QKV projections (batched z=3)
    gemm_f16<0><<<dim3(DD/GBN, NT/GBM, 3), blk, GEMM_SMEM>>>(
        qkva, WqkvT, bqkv, nullptr, qkvh, nullptr, DD, DD,
        nAct, (long long)DD * DD, DD, nAct);

    // 4) attention
    attn_kernel<<<BB * HH, blk, ATTN_SMEM>>>(qkvh, qkvh + nAct, qkvh + 2 * nAct, ctx);

    // 5) output projection
    gemm_f16<0><<<dim3(DD/GBN, NT/GBM, 1), blk, GEMM_SMEM>>>(
        ctx, WoT, bo, nullptr, attn, nullptr, DD, DD, 0, 0, 0, 0);

    // 6) LN1 + fp16 copy
    ln1_kernel<<<NT, blk>>>(q, attn, ln1g, ln1b, x, xh);

    // 7) gates
    gate_kernel<<<NT, blk>>>(x, Wg, bg, gates);

    // 8) MoE FFN1: hact[e] = gate[m,e] * gelu(x @ W1[e] + b1[e])
    gemm_f16<1><<<dim3(FF/GBN, NT/GBM, EE), blk, GEMM_SMEM>>>(
        xh, W1T, b1, gates, nullptr, hact, DD, FF,
        0, (long long)FF * DD, (long long)FF, (long long)NT * FF);

    // 9) MoE FFN2: moe = sum_e hact[e] @ W2[e]
    gemm_moe<<<dim3(DD/GBN, NT/GBM, 1), blk, GEMM_SMEM>>>(hact, W2T, moe);

    // 10) LN2 (adds gated expert biases)
    ln2_kernel<<<NT, blk>>>(x, moe, gates, b2, ln2g, ln2b, out);

    (void)in_sizes; (void)n_in; (void)out_size;
}

// round 6
// speedup vs baseline: 6.7206x; 1.0723x over previous
#include <cuda_runtime.h>
#include <cuda_fp16.h>
#include <math.h>
#include <stdint.h>

// Problem constants
#define BB 32
#define SS 196
#define DD 768
#define HH 12
#define DHH 64
#define EE 8
#define FF 3072
#define NT (BB*SS)          // 6272 tokens

// ---------------------------------------------------------------------------
// helpers
// ---------------------------------------------------------------------------
__device__ __forceinline__ uint32_t smem_u32(const void* p) {
    uint32_t a;
    asm("{ .reg .u64 t; cvta.to.shared.u64 t, %1; cvt.u32.u64 %0, t; }"
        : "=r"(a) : "l"(p));
    return a;
}

__device__ __forceinline__ void cpa16(uint32_t s, const void* g) {
    asm volatile("cp.async.cg.shared.global [%0], [%1], 16;" :: "r"(s), "l"(g));
}
__device__ __forceinline__ void cpa_commit() { asm volatile("cp.async.commit_group;"); }
template<int N> __device__ __forceinline__ void cpa_wait() {
    asm volatile("cp.async.wait_group %0;" :: "n"(N));
}

#define LDMX4(r, addr) \
    asm volatile("ldmatrix.sync.aligned.m8n8.x4.shared.b16 {%0,%1,%2,%3}, [%4];" \
        : "=r"((r)[0]), "=r"((r)[1]), "=r"((r)[2]), "=r"((r)[3]) : "r"(addr))

__device__ __forceinline__ void mma16816(float* d, const uint32_t* a, const uint32_t* b) {
    asm volatile("mma.sync.aligned.m16n8k16.row.col.f32.f16.f16.f32 "
        "{%0,%1,%2,%3}, {%4,%5,%6,%7}, {%8,%9}, {%0,%1,%2,%3};"
        : "+f"(d[0]), "+f"(d[1]), "+f"(d[2]), "+f"(d[3])
        : "r"(a[0]), "r"(a[1]), "r"(a[2]), "r"(a[3]), "r"(b[0]), "r"(b[1]));
}

__device__ __forceinline__ float gelu_exact(float v) {
    return 0.5f * v * (1.f + erff(v * 0.70710678118654752f));
}

// ---------------------------------------------------------------------------
// device scratch
// ---------------------------------------------------------------------------
__device__ __half g_qkva[(size_t)3*NT*DD];
__device__ float  g_qkvh[(size_t)3*NT*DD];
__device__ __half g_ctx[(size_t)NT*DD];
__device__ float  g_attn[(size_t)NT*DD];
__device__ float  g_x[(size_t)NT*DD];
__device__ __half g_xh[(size_t)NT*DD];
__device__ float  g_gates[(size_t)NT*EE];
__device__ __half g_hact[(size_t)EE*NT*FF];
__device__ float  g_moe[(size_t)NT*DD];
__device__ __half g_WqkvT[(size_t)3*DD*DD];
__device__ float  g_bqkv[(size_t)3*DD];
__device__ __half g_WoT[(size_t)DD*DD];
__device__ __half g_W1T[(size_t)EE*FF*DD];
__device__ __half g_W2T[(size_t)EE*DD*FF];

// ---------------------------------------------------------------------------
// conversion kernels
// ---------------------------------------------------------------------------
// converts 3 equal-size tensors in one launch
__global__ __launch_bounds__(256)
void convert3_h_kernel(const float* __restrict__ a, const float* __restrict__ b,
                       const float* __restrict__ c, __half* __restrict__ o, long long n)
{
    long long i = (long long)blockIdx.x * blockDim.x + threadIdx.x;
    const long long stride = (long long)gridDim.x * blockDim.x;
    for (; i < n; i += stride) {
        o[i]         = __float2half_rn(a[i]);
        o[n + i]     = __float2half_rn(b[i]);
        o[2 * n + i] = __float2half_rn(c[i]);
    }
}

__global__ __launch_bounds__(256)
void concat3_kernel(const float* __restrict__ a, const float* __restrict__ b,
                    const float* __restrict__ c, float* __restrict__ o)
{
    const int i = blockIdx.x * blockDim.x + threadIdx.x;
    if (i < DD) { o[i] = a[i]; o[DD + i] = b[i]; o[2 * DD + i] = c[i]; }
}

// in: [batch, K, N] fp32  ->  out: [batch, N, K] fp16
__global__ __launch_bounds__(256)
void transpose_h_kernel(const float* __restrict__ in, __half* __restrict__ o, int K, int N)
{
    __shared__ float t[32][33];
    const size_t bz = blockIdx.z;
    const float* ip = in + bz * (size_t)K * N;
    __half* op = o + bz * (size_t)K * N;
    const int k0 = blockIdx.y * 32, n0 = blockIdx.x * 32;
    const int tx = threadIdx.x, ty = threadIdx.y;
    #pragma unroll
    for (int j = 0; j < 4; j++)
        t[ty + j * 8][tx] = ip[(size_t)(k0 + ty + j * 8) * N + n0 + tx];
    __syncthreads();
    #pragma unroll
    for (int j = 0; j < 4; j++)
        op[(size_t)(n0 + ty + j * 8) * K + k0 + tx] = __float2half_rn(t[tx][ty + j * 8]);
}

// ---------------------------------------------------------------------------
// HMMA fp16 GEMM: C[M,N] = A[M,K] @ B[N,K]^T (+ bias)
// BM=128 BN=128 BK=64, 256 threads, warp tile 64x32 (grid 2m x 4n),
// 3-stage cp.async, 2 CTAs/SM (regs capped via launch_bounds).
// EPI 0: +bias -> fp32.   EPI 1: gate[m,e]*gelu(+bias) -> fp16.
// ---------------------------------------------------------------------------
#define GBM 128
#define GBN 128
#define GBK 64
#define RB 144
#define TILE_A (128 * RB)                  // 18432
#define TILE_B (128 * RB)                  // 18432
#define STAGE_BYTES (TILE_A + TILE_B)      // 36864
#define NSTAGE 3
#define GEMM_SMEM (NSTAGE * STAGE_BYTES)   // 110592

template<int EPI>
__global__ __launch_bounds__(256, 2)
void gemm_f16(const __half* __restrict__ A, const __half* __restrict__ B,
              const float* __restrict__ bias, const float* __restrict__ gates,
              float* __restrict__ C, __half* __restrict__ Ch,
              int K, int ldC,
              long long strA, long long strB, long long strBias, long long strC)
{
    extern __shared__ char smem[];
    const uint32_t smem_base = smem_u32(smem);

    const int tid = threadIdx.x;
    const int lane = tid & 31;
    const int wid = tid >> 5;
    const int wm = wid & 1;           // 64 rows
    const int wn = wid >> 1;          // 32 cols

    const long long bz = blockIdx.z;
    A += bz * strA;
    B += bz * strB;
    bias += bz * strBias;

    const int m0 = blockIdx.y * GBM;
    const int n0 = blockIdx.x * GBN;
    const int NC = K / GBK;

    auto load_stage = [&](int kc, int st) {
        const uint32_t sb = smem_base + st * STAGE_BYTES;
        const long long k0 = (long long)kc * GBK;
        #pragma unroll
        for (int i = tid; i < 1024; i += 256) {           // A: 128 rows x 8 vec16
            const int r = i >> 3;
            const int c = (i & 7) * 8;
            cpa16(sb + r * RB + c * 2, A + (size_t)(m0 + r) * K + k0 + c);
        }
        #pragma unroll
        for (int i = tid; i < 1024; i += 256) {           // B: 128 rows x 8 vec16
            const int r = i >> 3;
            const int c = (i & 7) * 8;
            cpa16(sb + TILE_A + r * RB + c * 2, B + (size_t)(n0 + r) * K + k0 + c);
        }
        cpa_commit();
    };

    load_stage(0, 0);
    if (NC > 1) load_stage(1, 1);

    float acc[4][4][4];
    #pragma unroll
    for (int i = 0; i < 4; i++)
        #pragma unroll
        for (int j = 0; j < 4; j++)
            #pragma unroll
            for (int r = 0; r < 4; r++) acc[i][j][r] = 0.f;

    const int a_row_in16 = lane & 15;
    const int a_col8 = (lane >> 4) * 8;
    const int b_row_in16 = ((lane >> 4) << 3) + (lane & 7);
    const int b_col8 = ((lane >> 3) & 1) * 8;

    for (int kc = 0; kc < NC; kc++) {
        cpa_wait<NSTAGE - 2>();
        __syncthreads();

        const uint32_t sa = smem_base + (kc % NSTAGE) * STAGE_BYTES;
        const uint32_t sbB = sa + TILE_A;

        #pragma unroll
        for (int ks = 0; ks < 4; ks++) {
            uint32_t af[4][4];
            uint32_t bf[4][2];
            #pragma unroll
            for (int ms = 0; ms < 4; ms++) {
                const uint32_t addr = sa
                    + (uint32_t)(wm * 64 + ms * 16 + a_row_in16) * RB
                    + (uint32_t)(a_col8 + ks * 16) * 2;
                LDMX4(af[ms], addr);
            }
            #pragma unroll
            for (int bs = 0; bs < 2; bs++) {
                uint32_t r[4];
                const uint32_t addr = sbB
                    + (uint32_t)(wn * 32 + bs * 16 + b_row_in16) * RB
                    + (uint32_t)(b_col8 + ks * 16) * 2;
                LDMX4(r, addr);
                bf[2 * bs][0] = r[0]; bf[2 * bs][1] = r[1];
                bf[2 * bs + 1][0] = r[2]; bf[2 * bs + 1][1] = r[3];
            }
            #pragma unroll
            for (int ms = 0; ms < 4; ms++)
                #pragma unroll
                for (int ns = 0; ns < 4; ns++)
                    mma16816(acc[ms][ns], af[ms], bf[ns]);
        }

        if (kc + NSTAGE - 1 < NC)
            load_stage(kc + NSTAGE - 1, (kc + NSTAGE - 1) % NSTAGE);
    }

    // ---- epilogue ----
    const int row_g = lane >> 2;
    const int col_g = (lane & 3) * 2;
    #pragma unroll
    for (int ms = 0; ms < 4; ms++) {
        const int mA = m0 + wm * 64 + ms * 16 + row_g;
        const int mB = mA + 8;
        float gA = 1.f, gB = 1.f;
        if (EPI == 1) {
            gA = gates[(size_t)mA * EE + bz];
            gB = gates[(size_t)mB * EE + bz];
        }
        #pragma unroll
        for (int ns = 0; ns < 4; ns++) {
            const int n = n0 + wn * 32 + ns * 8 + col_g;
            const float b0 = bias[n], b1 = bias[n + 1];
            if (EPI == 0) {
                float* Cb = C + bz * strC;
                float2 o0, o1;
                o0.x = acc[ms][ns][0] + b0;  o0.y = acc[ms][ns][1] + b1;
                o1.x = acc[ms][ns][2] + b0;  o1.y = acc[ms][ns][3] + b1;
                *(float2*)&Cb[(size_t)mA * ldC + n] = o0;
                *(float2*)&Cb[(size_t)mB * ldC + n] = o1;
            } else {
                __half* Cb = Ch + bz * strC;
                __half2 o0, o1;
                o0.x = __float2half_rn(gA * gelu_exact(acc[ms][ns][0] + b0));
                o0.y = __float2half_rn(gA * gelu_exact(acc[ms][ns][1] + b1));
                o1.x = __float2half_rn(gB * gelu_exact(acc[ms][ns][2] + b0));
                o1.y = __float2half_rn(gB * gelu_exact(acc[ms][ns][3] + b1));
                *(__half2*)&Cb[(size_t)mA * ldC + n] = o0;
                *(__half2*)&Cb[(size_t)mB * ldC + n] = o1;
            }
        }
    }
}

// ---------------------------------------------------------------------------
// MoE FFN2: moe[M,DD] = sum_e hact[e][M,FF] @ W2T[e][DD,FF]^T
// Same tiling as gemm_f16; flattened K over 8 experts x 48 chunks.
// ---------------------------------------------------------------------------
__global__ __launch_bounds__(256, 2)
void gemm_moe(const __half* __restrict__ Hact, const __half* __restrict__ W2T,
              float* __restrict__ Moe)
{
    extern __shared__ char smem[];
    const uint32_t smem_base = smem_u32(smem);

    const int tid = threadIdx.x;
    const int lane = tid & 31;
    const int wid = tid >> 5;
    const int wm = wid & 1;
    const int wn = wid >> 1;

    const int m0 = blockIdx.y * GBM;
    const int n0 = blockIdx.x * GBN;
    const int CPE = FF / GBK;               // 48
    const int NC = EE * CPE;                // 384

    auto load_stage = [&](int kc, int st) {
        const uint32_t sb = smem_base + st * STAGE_BYTES;
        const int e = kc / CPE;
        const long long k0 = (long long)(kc - e * CPE) * GBK;
        const __half* Ab = Hact + ((size_t)e * NT + m0) * FF + k0;
        const __half* Bb = W2T + ((size_t)e * DD + n0) * FF + k0;
        #pragma unroll
        for (int i = tid; i < 1024; i += 256) {
            const int r = i >> 3;
            const int c = (i & 7) * 8;
            cpa16(sb + r * RB + c * 2, Ab + (size_t)r * FF + c);
        }
        #pragma unroll
        for (int i = tid; i < 1024; i += 256) {
            const int r = i >> 3;
            const int c = (i & 7) * 8;
            cpa16(sb + TILE_A + r * RB + c * 2, Bb + (size_t)r * FF + c);
        }
        cpa_commit();
    };

    load_stage(0, 0);
    load_stage(1, 1);

    float acc[4][4][4];
    #pragma unroll
    for (int i = 0; i < 4; i++)
        #pragma unroll
        for (int j = 0; j < 4; j++)
            #pragma unroll
            for (int r = 0; r < 4; r++) acc[i][j][r] = 0.f;

    const int a_row_in16 = lane & 15;
    const int a_col8 = (lane >> 4) * 8;
    const int b_row_in16 = ((lane >> 4) << 3) + (lane & 7);
    const int b_col8 = ((lane >> 3) & 1) * 8;

    for (int kc = 0; kc < NC; kc++) {
        cpa_wait<NSTAGE - 2>();
        __syncthreads();

        const uint32_t sa = smem_base + (kc % NSTAGE) * STAGE_BYTES;
        const uint32_t sbB = sa + TILE_A;

        #pragma unroll
        for (int ks = 0; ks < 4; ks++) {
            uint32_t af[4][4];
            uint32_t bf[4][2];
            #pragma unroll
            for (int ms = 0; ms < 4; ms++) {
                const uint32_t addr = sa
                    + (uint32_t)(wm * 64 + ms * 16 + a_row_in16) * RB
                    + (uint32_t)(a_col8 + ks * 16) * 2;
                LDMX4(af[ms], addr);
            }
            #pragma unroll
            for (int bs = 0; bs < 2; bs++) {
                uint32_t r[4];
                const uint32_t addr = sbB
                    + (uint32_t)(wn * 32 + bs * 16 + b_row_in16) * RB
                    + (uint32_t)(b_col8 + ks * 16) * 2;
                LDMX4(r, addr);
                bf[2 * bs][0] = r[0]; bf[2 * bs][1] = r[1];
                bf[2 * bs + 1][0] = r[2]; bf[2 * bs + 1][1] = r[3];
            }
            #pragma unroll
            for (int ms = 0; ms < 4; ms++)
                #pragma unroll
                for (int ns = 0; ns < 4; ns++)
                    mma16816(acc[ms][ns], af[ms], bf[ns]);
        }

        if (kc + NSTAGE - 1 < NC)
            load_stage(kc + NSTAGE - 1, (kc + NSTAGE - 1) % NSTAGE);
    }

    const int row_g = lane >> 2;
    const int col_g = (lane & 3) * 2;
    #pragma unroll
    for (int ms = 0; ms < 4; ms++) {
        const int mA = m0 + wm * 64 + ms * 16 + row_g;
        const int mB = mA + 8;
        #pragma unroll
        for (int ns = 0; ns < 4; ns++) {
            const int n = n0 + wn * 32 + ns * 8 + col_g;
            float2 o0, o1;
            o0.x = acc[ms][ns][0];  o0.y = acc[ms][ns][1];
            o1.x = acc[ms][ns][2];  o1.y = acc[ms][ns][3];
            *(float2*)&Moe[(size_t)mA * DD + n] = o0;
            *(float2*)&Moe[(size_t)mB * DD + n] = o1;
        }
    }
}

// ---------------------------------------------------------------------------
// attention: per (b,h) block, 4-query blocking + float4 LDS, fp16 ctx out
// ---------------------------------------------------------------------------
#define AROW 68
#define ATTN_SMEM ((3 * SS * AROW + 32 * SS) * 4)

__global__ __launch_bounds__(256)
void attn_kernel(const float* __restrict__ qh, const float* __restrict__ kh,
                 const float* __restrict__ vh, __half* __restrict__ ctx)
{
    extern __shared__ float sm[];
    float* Qs = sm;
    float* Ks = Qs + SS * AROW;
    float* Vs = Ks + SS * AROW;
    float* Ps = Vs + SS * AROW;

    const int b = blockIdx.x / HH;
    const int h = blockIdx.x % HH;
    const int tid = threadIdx.x;
    const int lane = tid & 31;
    const int w = tid >> 5;

    const size_t base = ((size_t)b * SS) * DD + (size_t)h * DHH;
    for (int idx = tid; idx < SS * DHH; idx += 256) {
        const int r = idx >> 6, d = idx & 63;
        const size_t g = base + (size_t)r * DD + d;
        Qs[r * AROW + d] = qh[g];
        Ks[r * AROW + d] = kh[g];
        Vs[r * AROW + d] = vh[g];
    }
    __syncthreads();

    for (int qb = w; qb < 49; qb += 8) {
        const int q0 = qb * 4;
        float sl[4][7];

        {
            const float4* q0p = (const float4*)&Qs[(q0 + 0) * AROW];
            const float4* q1p = (const float4*)&Qs[(q0 + 1) * AROW];
            const float4* q2p = (const float4*)&Qs[(q0 + 2) * AROW];
            const float4* q3p = (const float4*)&Qs[(q0 + 3) * AROW];
            int slot = 0;
            for (int kk = lane; kk < SS; kk += 32, slot++) {
                const float4* kp = (const float4*)&Ks[kk * AROW];
                float s0 = 0.f, s1 = 0.f, s2 = 0.f, s3 = 0.f;
                #pragma unroll
                for (int d = 0; d < 16; d++) {
                    const float4 kv = kp[d];
                    float4 a;
                    a = q0p[d];
                    s0 = fmaf(a.x, kv.x, fmaf(a.y, kv.y, fmaf(a.z, kv.z, fmaf(a.w, kv.w, s0))));
                    a = q1p[d];
                    s1 = fmaf(a.x, kv.x, fmaf(a.y, kv.y, fmaf(a.z, kv.z, fmaf(a.w, kv.w, s1))));
                    a = q2p[d];
                    s2 = fmaf(a.x, kv.x, fmaf(a.y, kv.y, fmaf(a.z, kv.z, fmaf(a.w, kv.w, s2))));
                    a = q3p[d];
                    s3 = fmaf(a.x, kv.x, fmaf(a.y, kv.y, fmaf(a.z, kv.z, fmaf(a.w, kv.w, s3))));
                }
                sl[0][slot] = s0 * 0.125f;
                sl[1][slot] = s1 * 0.125f;
                sl[2][slot] = s2 * 0.125f;
                sl[3][slot] = s3 * 0.125f;
            }
        }

        #pragma unroll
        for (int qi = 0; qi < 4; qi++) {
            float mx = -1e30f;
            {
                int slot = 0;
                for (int kk = lane; kk < SS; kk += 32, slot++)
                    mx = fmaxf(mx, sl[qi][slot]);
            }
            #pragma unroll
            for (int off = 16; off; off >>= 1)
                mx = fmaxf(mx, __shfl_xor_sync(0xffffffffu, mx, off));
            float sum = 0.f;
            {
                int slot = 0;
                for (int kk = lane; kk < SS; kk += 32, slot++) {
                    const float p = __expf(sl[qi][slot] - mx);
                    sl[qi][slot] = p;
                    sum += p;
                }
            }
            #pragma unroll
            for (int off = 16; off; off >>= 1)
                sum += __shfl_xor_sync(0xffffffffu, sum, off);
            const float inv = 1.f / sum;
            {
                int slot = 0;
                for (int kk = lane; kk < SS; kk += 32, slot++)
                    Ps[(w * 4 + qi) * SS + kk] = sl[qi][slot] * inv;
            }
        }
        __syncwarp();

        float acc0[4] = {0.f, 0.f, 0.f, 0.f};
        float acc1[4] = {0.f, 0.f, 0.f, 0.f};
        for (int kk = 0; kk < SS; kk += 4) {
            float v0[4], v1[4];
            #pragma unroll
            for (int j = 0; j < 4; j++) {
                v0[j] = Vs[(kk + j) * AROW + lane];
                v1[j] = Vs[(kk + j) * AROW + lane + 32];
            }
            #pragma unroll
            for (int qi = 0; qi < 4; qi++) {
                const float4 p = *(const float4*)&Ps[(w * 4 + qi) * SS + kk];
                acc0[qi] = fmaf(p.x, v0[0], fmaf(p.y, v0[1], fmaf(p.z, v0[2], fmaf(p.w, v0[3], acc0[qi]))));
                acc1[qi] = fmaf(p.x, v1[0], fmaf(p.y, v1[1], fmaf(p.z, v1[2], fmaf(p.w, v1[3], acc1[qi]))));
            }
        }
        #pragma unroll
        for (int qi = 0; qi < 4; qi++) {
            const size_t o = base + (size_t)(q0 + qi) * DD;
            ctx[o + lane]      = __float2half_rn(acc0[qi]);
            ctx[o + lane + 32] = __float2half_rn(acc1[qi]);
        }
        __syncwarp();
    }
}

// ---------------------------------------------------------------------------
// LN / gate kernels
// ---------------------------------------------------------------------------
__device__ __forceinline__ float block_reduce_sum(float v, float* red)
{
    const int lane = threadIdx.x & 31, w = threadIdx.x >> 5;
    #pragma unroll
    for (int off = 16; off; off >>= 1) v += __shfl_xor_sync(0xffffffffu, v, off);
    if (lane == 0) red[w] = v;
    __syncthreads();
    if (w == 0) {
        float t = (lane < 8) ? red[lane] : 0.f;
        #pragma unroll
        for (int off = 4; off; off >>= 1) t += __shfl_xor_sync(0xffffffffu, t, off);
        if (lane == 0) red[0] = t;
    }
    __syncthreads();
    return red[0];
}

__global__ __launch_bounds__(256)
void ln1_kernel(const float* __restrict__ a, const float* __restrict__ b,
                const float* __restrict__ g, const float* __restrict__ beta,
                float* __restrict__ out, __half* __restrict__ oh)
{
    const int m = blockIdx.x;
    __shared__ float buf[DD];
    __shared__ float red1[32];
    __shared__ float red2[32];
    float s = 0.f;
    for (int d = threadIdx.x; d < DD; d += 256) {
        const float v = a[(size_t)m * DD + d] + b[(size_t)m * DD + d];
        buf[d] = v;
        s += v;
    }
    const float mean = block_reduce_sum(s, red1) * (1.f / DD);
    float s2 = 0.f;
    for (int d = threadIdx.x; d < DD; d += 256) {
        const float t = buf[d] - mean;
        s2 += t * t;
    }
    const float var = block_reduce_sum(s2, red2) * (1.f / DD);
    const float rstd = rsqrtf(var + 1e-5f);
    for (int d = threadIdx.x; d < DD; d += 256) {
        const float v = (buf[d] - mean) * rstd * g[d] + beta[d];
        out[(size_t)m * DD + d] = v;
        oh[(size_t)m * DD + d] = __float2half_rn(v);
    }
}

__global__ __launch_bounds__(256)
void gate_kernel(const float* __restrict__ x, const float* __restrict__ Wg,
                 const float* __restrict__ bg, float* __restrict__ gates)
{
    const int m = blockIdx.x;
    const int tid = threadIdx.x, lane = tid & 31, w = tid >> 5;
    float acc[EE] = {0, 0, 0, 0, 0, 0, 0, 0};
    const float* xr = x + (size_t)m * DD;
    for (int d = tid; d < DD; d += 256) {
        const float xv = xr[d];
        #pragma unroll
        for (int e = 0; e < EE; e++) acc[e] = fmaf(xv, Wg[d * EE + e], acc[e]);
    }
    #pragma unroll
    for (int e = 0; e < EE; e++)
        #pragma unroll
        for (int off = 16; off; off >>= 1) acc[e] += __shfl_xor_sync(0xffffffffu, acc[e], off);
    __shared__ float red[8][EE];
    if (lane == 0)
        #pragma unroll
        for (int e = 0; e < EE; e++) red[w][e] = acc[e];
    __syncthreads();
    if (tid == 0) {
        float v[EE];
        float mx = -1e30f;
        for (int e = 0; e < EE; e++) {
            float t = bg[e];
            for (int ww = 0; ww < 8; ww++) t += red[ww][e];
            v[e] = t;
            mx = fmaxf(mx, t);
        }
        float s = 0.f;
        for (int e = 0; e < EE; e++) { v[e] = __expf(v[e] - mx); s += v[e]; }
        const float inv = 1.f / s;
        for (int e = 0; e < EE; e++) gates[(size_t)m * EE + e] = v[e] * inv;
    }
}

// LN2: out = LN(x + moe + sum_e gates[e]*b2[e])
__global__ __launch_bounds__(256)
void ln2_kernel(const float* __restrict__ x, const float* __restrict__ moe,
                const float* __restrict__ gates, const float* __restrict__ b2,
                const float* __restrict__ g, const float* __restrict__ beta,
                float* __restrict__ out)
{
    const int m = blockIdx.x;
    __shared__ float buf[DD];
    __shared__ float gl[EE];
    __shared__ float red1[32];
    __shared__ float red2[32];
    if (threadIdx.x < EE) gl[threadIdx.x] = gates[(size_t)m * EE + threadIdx.x];
    __syncthreads();
    float s = 0.f;
    for (int d = threadIdx.x; d < DD; d += 256) {
        float bsum = 0.f;
        #pragma unroll
        for (int e = 0; e < EE; e++)
            bsum = fmaf(gl[e], b2[(size_t)e * DD + d], bsum);
        const float v = x[(size_t)m * DD + d] + moe[(size_t)m * DD + d] + bsum;
        buf[d] = v;
        s += v;
    }
    const float mean = block_reduce_sum(s, red1) * (1.f / DD);
    float s2 = 0.f;
    for (int d = threadIdx.x; d < DD; d += 256) {
        const float t = buf[d] - mean;
        s2 += t * t;
    }
    const float var = block_reduce_sum(s2, red2) * (1.f / DD);
    const float rstd = rsqrtf(var + 1e-5f);
    for (int d = threadIdx.x; d < DD; d += 256)
        out[(size_t)m * DD + d] = (buf[d] - mean) * rstd * g[d] + beta[d];
}

// ---------------------------------------------------------------------------
// launch
// ---------------------------------------------------------------------------
extern "C" void kernel_launch(void* const* d_in, const int* in_sizes, int n_in,
                              void* d_out, int out_size)
{
    const float* q    = (const float*)d_in[0];
    const float* k    = (const float*)d_in[1];
    const float* v    = (const float*)d_in[2];
    const float* Wq   = (const float*)d_in[3];
    const float* bq   = (const float*)d_in[4];
    const float* Wk   = (const float*)d_in[5];
    const float* bk   = (const float*)d_in[6];
    const float* Wv   = (const float*)d_in[7];
    const float* bv   = (const float*)d_in[8];
    const float* Wo   = (const float*)d_in[9];
    const float* bo   = (const float*)d_in[10];
    const float* ln1g = (const float*)d_in[11];
    const float* ln1b = (const float*)d_in[12];
    const float* ln2g = (const float*)d_in[13];
    const float* ln2b = (const float*)d_in[14];
    const float* Wg   = (const float*)d_in[15];
    const float* bg   = (const float*)d_in[16];
    const float* W1   = (const float*)d_in[17];
    const float* b1   = (const float*)d_in[18];
    const float* W2   = (const float*)d_in[19];
    const float* b2   = (const float*)d_in[20];
    float* out = (float*)d_out;

    __half *qkva, *ctx, *xh, *hact, *WqkvT, *WoT, *W1T, *W2T;
    float *qkvh, *attn, *x, *gates, *moe, *bqkv;
    cudaGetSymbolAddress((void**)&qkva, g_qkva);
    cudaGetSymbolAddress((void**)&qkvh, g_qkvh);
    cudaGetSymbolAddress((void**)&ctx, g_ctx);
    cudaGetSymbolAddress((void**)&attn, g_attn);
    cudaGetSymbolAddress((void**)&x, g_x);
    cudaGetSymbolAddress((void**)&xh, g_xh);
    cudaGetSymbolAddress((void**)&gates, g_gates);
    cudaGetSymbolAddress((void**)&hact, g_hact);
    cudaGetSymbolAddress((void**)&moe, g_moe);
    cudaGetSymbolAddress((void**)&WqkvT, g_WqkvT);
    cudaGetSymbolAddress((void**)&bqkv, g_bqkv);
    cudaGetSymbolAddress((void**)&WoT, g_WoT);
    cudaGetSymbolAddress((void**)&W1T, g_W1T);
    cudaGetSymbolAddress((void**)&W2T, g_W2T);

    cudaFuncSetAttribute(attn_kernel, cudaFuncAttributeMaxDynamicSharedMemorySize, ATTN_SMEM);
    cudaFuncSetAttribute(gemm_f16<0>, cudaFuncAttributeMaxDynamicSharedMemorySize, GEMM_SMEM);
    cudaFuncSetAttribute(gemm_f16<1>, cudaFuncAttributeMaxDynamicSharedMemorySize, GEMM_SMEM);
    cudaFuncSetAttribute(gemm_moe,   cudaFuncAttributeMaxDynamicSharedMemorySize, GEMM_SMEM);

    const dim3 blk(256);
    const long long nAct = (long long)NT * DD;

    // 1) convert inputs to fp16 (one launch, contiguous q|k|v)
    convert3_h_kernel<<<1024, blk>>>(q, k, v, qkva, nAct);

    // 2) transpose + convert weights
    transpose_h_kernel<<<dim3(DD/32, DD/32, 1), dim3(32, 8)>>>(Wq, WqkvT, DD, DD);
    transpose_h_kernel<<<dim3(DD/32, DD/32, 1), dim3(32, 8)>>>(Wk, WqkvT + (size_t)DD*DD, DD, DD);
    transpose_h_kernel<<<dim3(DD/32, DD/32, 1), dim3(32, 8)>>>(Wv, WqkvT + 2*(size_t)DD*DD, DD, DD);
    transpose_h_kernel<<<dim3(DD/32, DD/32, 1), dim3(32, 8)>>>(Wo, WoT, DD, DD);
    transpose_h_kernel<<<dim3(FF/32, DD/32, EE), dim3(32, 8)>>>(W1, W1T, DD, FF);
    transpose_h_kernel<<<dim3(DD/32, FF/32, EE), dim3(32, 8)>>>(W2, W2T, FF, DD);
    concat3_kernel<<<3, blk>>>(bq, bk, bv, bqkv);

    // 3) QKV projections (batched z=3)
    gemm_f16<0><<<dim3(DD/GBN, NT/GBM, 3), blk, GEMM_SMEM>>>(
        qkva, WqkvT, bqkv, nullptr, qkvh, nullptr, DD, DD,
        nAct, (long long)DD * DD, DD, nAct);

    // 4) attention
    attn_kernel<<<BB * HH, blk, ATTN_SMEM>>>(qkvh, qkvh + nAct, qkvh + 2 * nAct, ctx);

    // 5) output projection
    gemm_f16<0><<<dim3(DD/GBN, NT/GBM, 1), blk, GEMM_SMEM>>>(
        ctx, WoT, bo, nullptr, attn, nullptr, DD, DD, 0, 0, 0, 0);

    // 6) LN1 + fp16 copy
    ln1_kernel<<<NT, blk>>>(q, attn, ln1g, ln1b, x, xh);

    // 7) gates
    gate_kernel<<<NT, blk>>>(x, Wg, bg, gates);

    // 8) MoE FFN1: hact[e] = gate[m,e] * gelu(x @ W1[e] + b1[e])
    gemm_f16<1><<<dim3(FF/GBN, NT/GBM, EE), blk, GEMM_SMEM>>>(
        xh, W1T, b1, gates, nullptr, hact, DD, FF,
        0, (long long)FF * DD, (long long)FF, (long long)NT * FF);

    // 9) MoE FFN2: moe = sum_e hact[e] @ W2[e]
    gemm_moe<<<dim3(DD/GBN, NT/GBM, 1), blk, GEMM_SMEM>>>(hact, W2T, moe);

    // 10) LN2 (adds gated expert biases)
    ln2_kernel<<<NT, blk>>>(x, moe, gates, b2, ln2g, ln2b, out);

    (void)in_sizes; (void)n_in; (void)out_size;
}